// round 14
// baseline (speedup 1.0000x reference)
#include <cuda_runtime.h>
#include <cuda_bf16.h>
#include <cstdint>

#define NN 100000
#define EE 1600000
#define NBLK 98          // ceil(NN/1024)
#define GB1 1563         // gemm1 blocks: ceil(NN/64)
#define GB2 782          // gemm2 blocks: ceil(NN/128)

#define SAS 272          // gemm1 smem row stride (bytes)
#define S2AS 144         // gemm2 smem row stride (bytes)

// ---------------- scratch ----------------
__device__ __align__(16) float g_h0[NN * 64];
__device__ __align__(16) float g_h1[NN * 64];
__device__ __align__(16) float g_h2[NN * 40];
__device__ float g_adst[NN];
__device__ float g_asrc[NN];
__device__ float g_wself[NN];
__device__ int   g_rowptr[NN + 1];
__device__ int   g_cursor[NN];   // zero at load; re-zeroed by agg1 tail each call
__device__ int   g_col[EE];
__device__ __align__(16) int g_rank[EE];  // per-edge rank within its dst (from hist)
__device__ int   g_bsum[128];    // re-zeroed by prep each call
// pre-swizzled W tiles (hi/lo bf16, exact smem layout incl. padding)
__device__ __align__(16) char g_w0h[64 * SAS];
__device__ __align__(16) char g_w0l[64 * SAS];
__device__ __align__(16) char g_w1h[40 * S2AS];
__device__ __align__(16) char g_w1l[40 * S2AS];

__device__ __forceinline__ float lrelu(float x) { return x < 0.f ? 0.2f * x : x; }

// ---------------- warp mma helper (sm_80+ baseline PTX; HMMA on Blackwell) ----------
__device__ __forceinline__ void mma16816(float* c, const uint32_t* a, const uint32_t* b) {
    asm volatile(
        "mma.sync.aligned.m16n8k16.row.col.f32.bf16.bf16.f32 "
        "{%0,%1,%2,%3}, {%4,%5,%6,%7}, {%8,%9}, {%0,%1,%2,%3};"
        : "+f"(c[0]), "+f"(c[1]), "+f"(c[2]), "+f"(c[3])
        : "r"(a[0]), "r"(a[1]), "r"(a[2]), "r"(a[3]), "r"(b[0]), "r"(b[1]));
}

// paired split-convert: hi = {bf16(y), bf16(x)}, lo = {bf16(y-hi.y), bf16(x-hi.x)}
__device__ __forceinline__ void cvt_split2(float x, float y, uint32_t& hi, uint32_t& lo) {
    asm("cvt.rn.bf16x2.f32 %0, %1, %2;" : "=r"(hi) : "f"(y), "f"(x));
    float lx = x - __uint_as_float(hi << 16);
    float ly = y - __uint_as_float(hi & 0xFFFF0000u);
    asm("cvt.rn.bf16x2.f32 %0, %1, %2;" : "=r"(lo) : "f"(ly), "f"(lx));
}

// ---------------- prep: convert W0/W1 once into pre-swizzled hi/lo buffers ----------
__global__ void __launch_bounds__(256) prep_w_kernel(const float* __restrict__ W0,
                                                     const float* __restrict__ W1,
                                                     int* __restrict__ bsum) {
    int tid = blockIdx.x * 256 + threadIdx.x;
    if (tid < 128) bsum[tid] = 0;
    if (tid < 64 * 32) {
        int r = tid >> 5, c4 = tid & 31;
        float4 v = reinterpret_cast<const float4*>(W0)[r * 32 + c4];
        uint2 hi, lo;
        cvt_split2(v.x, v.y, hi.x, lo.x);
        cvt_split2(v.z, v.w, hi.y, lo.y);
        int off = r * SAS + c4 * 8;
        *reinterpret_cast<uint2*>(g_w0h + off) = hi;
        *reinterpret_cast<uint2*>(g_w0l + off) = lo;
    }
    int t1 = tid - 64 * 32;
    if (t1 >= 0 && t1 < 40 * 16) {
        int r = t1 >> 4, c4 = t1 & 15;
        float4 v = reinterpret_cast<const float4*>(W1)[r * 16 + c4];
        uint2 hi, lo;
        cvt_split2(v.x, v.y, hi.x, lo.x);
        cvt_split2(v.z, v.w, hi.y, lo.y);
        int off = r * S2AS + c4 * 8;
        *reinterpret_cast<uint2*>(g_w1h + off) = hi;
        *reinterpret_cast<uint2*>(g_w1l + off) = lo;
    }
}

// ---------------- layer-1 GEMM: M=64 tiles, 3 CTAs/SM, bf16 2-term split ------------
// Embedded histogram also records each edge's rank (atomicAdd return) -> g_rank,
// turning the later scatter into an atomic-free deterministic-slot store.
#define SM_ATT 0
#define SM_PD  512
#define SM_PS  768
#define SM_AHI 1024
#define SM_ALO (SM_AHI + 64 * SAS)
#define SM_BHI (SM_ALO + 64 * SAS)
#define SM_BLO (SM_BHI + 64 * SAS)
#define SM_TOT (SM_BLO + 64 * SAS)

__global__ void __launch_bounds__(256) gemm1_mma_kernel(
    const float* __restrict__ A, const float* __restrict__ att, float* __restrict__ C,
    float* __restrict__ adst, float* __restrict__ asrc, float* __restrict__ wself,
    const int* __restrict__ ei, int* __restrict__ deg, int* __restrict__ rank) {
    extern __shared__ char ds[];
    int tid = threadIdx.x;
    int row0 = blockIdx.x * 64;

    // embedded degree histogram + rank capture: 1024 edges per CTA
    {
        int t4 = blockIdx.x * 256 + tid;
        if (t4 < EE / 4) {
            int4 d4 = reinterpret_cast<const int4*>(ei + EE)[t4];
            int4 r4;
            r4.x = atomicAdd(deg + d4.x, 1);
            r4.y = atomicAdd(deg + d4.y, 1);
            r4.z = atomicAdd(deg + d4.z, 1);
            r4.w = atomicAdd(deg + d4.w, 1);
            reinterpret_cast<int4*>(rank)[t4] = r4;
        }
    }

    float* att_s = reinterpret_cast<float*>(ds + SM_ATT);
    float* spd = reinterpret_cast<float*>(ds + SM_PD);
    float* sps = reinterpret_cast<float*>(ds + SM_PS);
    if (tid < 128) att_s[tid] = __ldg(att + tid);
    if (tid < 64) {
        spd[tid] = 0.f;
        sps[tid] = 0.f;
    }

    // A tile: 64x128 fp32 -> bf16 hi/lo via paired cvt
    const float4* A4 = reinterpret_cast<const float4*>(A);
    for (int idx = tid; idx < 64 * 32; idx += 256) {
        int r = idx >> 5, c4 = idx & 31;
        float4 v = make_float4(0.f, 0.f, 0.f, 0.f);
        int gn = row0 + r;
        if (gn < NN) v = A4[gn * 32 + c4];
        uint2 hi, lo;
        cvt_split2(v.x, v.y, hi.x, lo.x);
        cvt_split2(v.z, v.w, hi.y, lo.y);
        int off = r * SAS + c4 * 8;
        *reinterpret_cast<uint2*>(ds + SM_AHI + off) = hi;
        *reinterpret_cast<uint2*>(ds + SM_ALO + off) = lo;
    }
    // B tile: plain uint4 copy of pre-swizzled W0 (L2-resident)
    for (int idx = tid; idx < 64 * SAS / 16; idx += 256) {
        reinterpret_cast<uint4*>(ds + SM_BHI)[idx] =
            reinterpret_cast<const uint4*>(g_w0h)[idx];
        reinterpret_cast<uint4*>(ds + SM_BLO)[idx] =
            reinterpret_cast<const uint4*>(g_w0l)[idx];
    }
    __syncthreads();

    int wid = tid >> 5;
    int lane = tid & 31;
    int wm = wid & 3;
    int wn = wid >> 2;
    int g = lane >> 2;
    int t = lane & 3;

    float c[4][4];
#pragma unroll
    for (int nt = 0; nt < 4; ++nt)
#pragma unroll
        for (int q = 0; q < 4; ++q) c[nt][q] = 0.f;

    int arow = (wm * 16 + g) * SAS + t * 4;
    int brow = (wn * 32 + g) * SAS + t * 4;

#pragma unroll
    for (int kk = 0; kk < 8; ++kk) {
        int kb = kk * 32;
        uint32_t aH[4], aL[4], bH[4][2], bL[4][2];
        int base = arow + kb;
        aH[0] = *reinterpret_cast<const uint32_t*>(ds + SM_AHI + base);
        aH[1] = *reinterpret_cast<const uint32_t*>(ds + SM_AHI + base + 8 * SAS);
        aH[2] = *reinterpret_cast<const uint32_t*>(ds + SM_AHI + base + 16);
        aH[3] = *reinterpret_cast<const uint32_t*>(ds + SM_AHI + base + 8 * SAS + 16);
        aL[0] = *reinterpret_cast<const uint32_t*>(ds + SM_ALO + base);
        aL[1] = *reinterpret_cast<const uint32_t*>(ds + SM_ALO + base + 8 * SAS);
        aL[2] = *reinterpret_cast<const uint32_t*>(ds + SM_ALO + base + 16);
        aL[3] = *reinterpret_cast<const uint32_t*>(ds + SM_ALO + base + 8 * SAS + 16);
#pragma unroll
        for (int nt = 0; nt < 4; ++nt) {
            int bb = brow + nt * 8 * SAS + kb;
            bH[nt][0] = *reinterpret_cast<const uint32_t*>(ds + SM_BHI + bb);
            bH[nt][1] = *reinterpret_cast<const uint32_t*>(ds + SM_BHI + bb + 16);
            bL[nt][0] = *reinterpret_cast<const uint32_t*>(ds + SM_BLO + bb);
            bL[nt][1] = *reinterpret_cast<const uint32_t*>(ds + SM_BLO + bb + 16);
        }
#pragma unroll
        for (int nt = 0; nt < 4; ++nt) {
            mma16816(c[nt], aH, bH[nt]);
            mma16816(c[nt], aH, bL[nt]);
            mma16816(c[nt], aL, bH[nt]);
        }
    }

    // epilogue: store C + alpha dot partials (quad reduce -> smem atomics)
    int lr0 = wm * 16 + g, lr1 = lr0 + 8;
    int gn0 = row0 + lr0, gn1 = row0 + lr1;
    float pd0 = 0.f, ps0 = 0.f, pd1 = 0.f, ps1 = 0.f;
#pragma unroll
    for (int nt = 0; nt < 4; ++nt) {
        int col = wn * 32 + nt * 8 + 2 * t;
        float c0 = c[nt][0], c1 = c[nt][1], c2 = c[nt][2], c3 = c[nt][3];
        pd0 += c0 * att_s[col] + c1 * att_s[col + 1];
        ps0 += c0 * att_s[64 + col] + c1 * att_s[64 + col + 1];
        pd1 += c2 * att_s[col] + c3 * att_s[col + 1];
        ps1 += c2 * att_s[64 + col] + c3 * att_s[64 + col + 1];
        if (gn0 < NN)
            *reinterpret_cast<float2*>(C + (size_t)gn0 * 64 + col) = make_float2(c0, c1);
        if (gn1 < NN)
            *reinterpret_cast<float2*>(C + (size_t)gn1 * 64 + col) = make_float2(c2, c3);
    }
#pragma unroll
    for (int o = 1; o <= 2; o <<= 1) {
        pd0 += __shfl_down_sync(0xffffffffu, pd0, o);
        ps0 += __shfl_down_sync(0xffffffffu, ps0, o);
        pd1 += __shfl_down_sync(0xffffffffu, pd1, o);
        ps1 += __shfl_down_sync(0xffffffffu, ps1, o);
    }
    if (t == 0) {
        atomicAdd(spd + lr0, pd0);
        atomicAdd(sps + lr0, ps0);
        atomicAdd(spd + lr1, pd1);
        atomicAdd(sps + lr1, ps1);
    }
    __syncthreads();
    if (tid < 64) {
        int gn = row0 + tid;
        if (gn < NN) {
            float pd = spd[tid], ps = sps[tid];
            adst[gn] = pd;
            asrc[gn] = ps;
            wself[gn] = __expf(lrelu(pd + ps));
        }
    }
}

// ---------------- layer-2 GEMM (warp mma, bf16 2-term split, M=128 N=40 K=64) --------
#define S2_ATT 0
#define S2_AHI 512
#define S2_ALO (S2_AHI + 128 * S2AS)
#define S2_BHI (S2_ALO + 128 * S2AS)
#define S2_BLO (S2_BHI + 40 * S2AS)
#define S2_TOT (S2_BLO + 40 * S2AS)

__global__ void __launch_bounds__(256) gemm2_mma_kernel(
    const float* __restrict__ A, const float* __restrict__ att, float* __restrict__ C,
    float* __restrict__ adst, float* __restrict__ asrc, float* __restrict__ wself) {
    extern __shared__ char ds[];
    int tid = threadIdx.x;
    int row0 = blockIdx.x * 128;

    float* att_s = reinterpret_cast<float*>(ds + S2_ATT);
    if (tid < 80) att_s[tid] = __ldg(att + tid);

    const float4* A4 = reinterpret_cast<const float4*>(A);
    for (int idx = tid; idx < 128 * 16; idx += 256) {
        int r = idx >> 4, c4 = idx & 15;
        float4 v = make_float4(0.f, 0.f, 0.f, 0.f);
        int gn = row0 + r;
        if (gn < NN) v = A4[gn * 16 + c4];
        uint2 hi, lo;
        cvt_split2(v.x, v.y, hi.x, lo.x);
        cvt_split2(v.z, v.w, hi.y, lo.y);
        int off = r * S2AS + c4 * 8;
        *reinterpret_cast<uint2*>(ds + S2_AHI + off) = hi;
        *reinterpret_cast<uint2*>(ds + S2_ALO + off) = lo;
    }
    for (int idx = tid; idx < 40 * S2AS / 16; idx += 256) {
        reinterpret_cast<uint4*>(ds + S2_BHI)[idx] =
            reinterpret_cast<const uint4*>(g_w1h)[idx];
        reinterpret_cast<uint4*>(ds + S2_BLO)[idx] =
            reinterpret_cast<const uint4*>(g_w1l)[idx];
    }
    __syncthreads();

    int wid = tid >> 5;
    int lane = tid & 31;
    int g = lane >> 2;
    int t = lane & 3;

    float c[5][4];
#pragma unroll
    for (int nt = 0; nt < 5; ++nt)
#pragma unroll
        for (int q = 0; q < 4; ++q) c[nt][q] = 0.f;

    int arow = (wid * 16 + g) * S2AS + t * 4;
    int brow = g * S2AS + t * 4;

#pragma unroll
    for (int kk = 0; kk < 4; ++kk) {
        int kb = kk * 32;
        uint32_t aH[4], aL[4], bH[5][2], bL[5][2];
        int base = arow + kb;
        aH[0] = *reinterpret_cast<const uint32_t*>(ds + S2_AHI + base);
        aH[1] = *reinterpret_cast<const uint32_t*>(ds + S2_AHI + base + 8 * S2AS);
        aH[2] = *reinterpret_cast<const uint32_t*>(ds + S2_AHI + base + 16);
        aH[3] = *reinterpret_cast<const uint32_t*>(ds + S2_AHI + base + 8 * S2AS + 16);
        aL[0] = *reinterpret_cast<const uint32_t*>(ds + S2_ALO + base);
        aL[1] = *reinterpret_cast<const uint32_t*>(ds + S2_ALO + base + 8 * S2AS);
        aL[2] = *reinterpret_cast<const uint32_t*>(ds + S2_ALO + base + 16);
        aL[3] = *reinterpret_cast<const uint32_t*>(ds + S2_ALO + base + 8 * S2AS + 16);
#pragma unroll
        for (int nt = 0; nt < 5; ++nt) {
            int bb = brow + nt * 8 * S2AS + kb;
            bH[nt][0] = *reinterpret_cast<const uint32_t*>(ds + S2_BHI + bb);
            bH[nt][1] = *reinterpret_cast<const uint32_t*>(ds + S2_BHI + bb + 16);
            bL[nt][0] = *reinterpret_cast<const uint32_t*>(ds + S2_BLO + bb);
            bL[nt][1] = *reinterpret_cast<const uint32_t*>(ds + S2_BLO + bb + 16);
        }
#pragma unroll
        for (int nt = 0; nt < 5; ++nt) {
            mma16816(c[nt], aH, bH[nt]);
            mma16816(c[nt], aH, bL[nt]);
            mma16816(c[nt], aL, bH[nt]);
        }
    }

    int lr0 = wid * 16 + g, lr1 = lr0 + 8;
    int gn0 = row0 + lr0, gn1 = row0 + lr1;
    float pd0 = 0.f, ps0 = 0.f, pd1 = 0.f, ps1 = 0.f;
#pragma unroll
    for (int nt = 0; nt < 5; ++nt) {
        int col = nt * 8 + 2 * t;
        float c0 = c[nt][0], c1 = c[nt][1], c2 = c[nt][2], c3 = c[nt][3];
        pd0 += c0 * att_s[col] + c1 * att_s[col + 1];
        ps0 += c0 * att_s[40 + col] + c1 * att_s[40 + col + 1];
        pd1 += c2 * att_s[col] + c3 * att_s[col + 1];
        ps1 += c2 * att_s[40 + col] + c3 * att_s[40 + col + 1];
        if (gn0 < NN)
            *reinterpret_cast<float2*>(C + (size_t)gn0 * 40 + col) = make_float2(c0, c1);
        if (gn1 < NN)
            *reinterpret_cast<float2*>(C + (size_t)gn1 * 40 + col) = make_float2(c2, c3);
    }
#pragma unroll
    for (int o = 1; o <= 2; o <<= 1) {
        pd0 += __shfl_down_sync(0xffffffffu, pd0, o);
        ps0 += __shfl_down_sync(0xffffffffu, ps0, o);
        pd1 += __shfl_down_sync(0xffffffffu, pd1, o);
        ps1 += __shfl_down_sync(0xffffffffu, ps1, o);
    }
    if (t == 0) {
        if (gn0 < NN) {
            adst[gn0] = pd0;
            asrc[gn0] = ps0;
            wself[gn0] = __expf(lrelu(pd0 + ps0));
        }
        if (gn1 < NN) {
            adst[gn1] = pd1;
            asrc[gn1] = ps1;
            wself[gn1] = __expf(lrelu(pd1 + ps1));
        }
    }
}

// ---------------- CSR build: fused scan with decoupled lookback ----------------
#define SCAN_FLAG 0x40000000

__global__ void __launch_bounds__(1024) scan_fused_kernel(
    const int* __restrict__ deg, int* __restrict__ rowp, int* __restrict__ cursor,
    int* __restrict__ partial) {
    __shared__ int wsum[32];
    __shared__ int s_off;
    int tid = threadIdx.x, b = blockIdx.x;
    int lane = tid & 31, w = tid >> 5;
    int i = b * 1024 + tid;
    int v = (i < NN) ? deg[i] : 0;

    int x = v;
#pragma unroll
    for (int o = 1; o < 32; o <<= 1) {
        int y = __shfl_up_sync(0xffffffffu, x, o);
        if (lane >= o) x += y;
    }
    if (lane == 31) wsum[w] = x;
    __syncthreads();
    if (w == 0) {
        int s = wsum[lane];
#pragma unroll
        for (int o = 1; o < 32; o <<= 1) {
            int y = __shfl_up_sync(0xffffffffu, s, o);
            if (lane >= o) s += y;
        }
        wsum[lane] = s;
        if (lane == 31) {
            atomicExch(partial + b, s | SCAN_FLAG);
        }
        int acc = 0;
        for (int j = lane; j < b; j += 32) {
            int p;
            do {
                p = *((volatile int*)(partial + j));
            } while (!(p & SCAN_FLAG));
            acc += p & (SCAN_FLAG - 1);
        }
#pragma unroll
        for (int o = 16; o; o >>= 1) acc += __shfl_xor_sync(0xffffffffu, acc, o);
        if (lane == 0) s_off = acc;
    }
    __syncthreads();
    int excl = ((w == 0) ? 0 : wsum[w - 1]) + x - v + s_off;
    if (i < NN) {
        rowp[i] = excl;
        cursor[i] = excl;
    }
    if (i == 0) rowp[NN] = EE;
}

// ---------------- scatter: atomic-free deterministic slots ----------------
// col[rowp[d] + rank[e]] = s. rank computed during the (hidden) hist in gemm1.
__global__ void __launch_bounds__(256) scatter_kernel(
    const int* __restrict__ ei, const int* __restrict__ rowp,
    const int* __restrict__ rank, int* __restrict__ col) {
    int t = blockIdx.x * 256 + threadIdx.x;
    if (t < EE / 4) {
        int4 s4 = reinterpret_cast<const int4*>(ei)[t];
        int4 d4 = reinterpret_cast<const int4*>(ei + EE)[t];
        int4 r4 = reinterpret_cast<const int4*>(rank)[t];
        col[__ldg(rowp + d4.x) + r4.x] = s4.x;
        col[__ldg(rowp + d4.y) + r4.y] = s4.y;
        col[__ldg(rowp + d4.z) + r4.z] = s4.z;
        col[__ldg(rowp + d4.w) + r4.w] = s4.w;
    }
}

// ---------------- aggregation: shfl-free gather, inline edge weights ----------------
// czero (nullable): buffer to zero for the next replay (cursor, consumed by hist).
template <int CH, bool RELU, bool LSM>
__global__ void aggregate_kernel(const float* __restrict__ h, const float* __restrict__ adst,
                                 const float* __restrict__ asrc,
                                 const float* __restrict__ wself,
                                 const int* __restrict__ rowp, const int* __restrict__ col,
                                 float* __restrict__ out, int* __restrict__ czero) {
    constexpr int NL = CH / 4;    // 16 or 10
    constexpr int NG = 32 / NL;   // 2 or 3

    int gtid = blockIdx.x * blockDim.x + threadIdx.x;
    if (czero != nullptr && gtid < NN) czero[gtid] = 0;

    int d = gtid >> 5;
    int lane = threadIdx.x & 31;
    if (d >= NN) return;

    int rs = __ldg(rowp + d), re = __ldg(rowp + d + 1);
    float ad = __ldg(adst + d);

    int group = lane / NL;
    if (group >= NG) group = NG - 1;
    int cid = lane - group * NL;
    if (cid >= NL) cid -= NL;

    const float4* __restrict__ h4 = reinterpret_cast<const float4*>(h);

    float4 acc = make_float4(0.f, 0.f, 0.f, 0.f);
    float psum = 0.f;

    for (int j = rs + group; j < re; j += NG) {
        int s = __ldg(col + j);
        float e = __expf(lrelu(ad + __ldg(asrc + s)));
        float4 hv = __ldg(h4 + s * NL + cid);
        psum += e;
        acc.x += e * hv.x;
        acc.y += e * hv.y;
        acc.z += e * hv.z;
        acc.w += e * hv.w;
    }

    float es = __ldg(wself + d);

    if (group == 0 && lane < NL) {
        float4 hv = __ldg(h4 + d * NL + cid);
        acc.x += es * hv.x;
        acc.y += es * hv.y;
        acc.z += es * hv.z;
        acc.w += es * hv.w;
    }

#pragma unroll
    for (int g = 1; g < NG; ++g) {
        int sl = lane + g * NL;
        float px = __shfl_sync(0xffffffffu, acc.x, sl & 31);
        float py = __shfl_sync(0xffffffffu, acc.y, sl & 31);
        float pz = __shfl_sync(0xffffffffu, acc.z, sl & 31);
        float pw = __shfl_sync(0xffffffffu, acc.w, sl & 31);
        float pp = __shfl_sync(0xffffffffu, psum, g * NL);
        if (lane < NL) {
            acc.x += px;
            acc.y += py;
            acc.z += pz;
            acc.w += pw;
        }
        psum = (lane == 0) ? psum + pp : psum;
    }
    psum = __shfl_sync(0xffffffffu, psum, 0) + es;

    float4 v = make_float4(0.f, 0.f, 0.f, 0.f);
    if (lane < NL) {
        float inv = 1.0f / psum;
        v.x = acc.x * inv;
        v.y = acc.y * inv;
        v.z = acc.z * inv;
        v.w = acc.w * inv;
    }

    if (LSM) {
        float vm = -1e30f;
        if (lane < NL) vm = fmaxf(fmaxf(v.x, v.y), fmaxf(v.z, v.w));
#pragma unroll
        for (int o = 16; o; o >>= 1) vm = fmaxf(vm, __shfl_xor_sync(0xffffffffu, vm, o));
        float se = 0.f;
        if (lane < NL)
            se = __expf(v.x - vm) + __expf(v.y - vm) + __expf(v.z - vm) + __expf(v.w - vm);
#pragma unroll
        for (int o = 16; o; o >>= 1) se += __shfl_xor_sync(0xffffffffu, se, o);
        float l = vm + logf(se);
        if (lane < NL) {
            v.x -= l;
            v.y -= l;
            v.z -= l;
            v.w -= l;
            reinterpret_cast<float4*>(out)[(size_t)d * NL + cid] = v;
        }
    } else {
        if (lane < NL) {
            if (RELU) {
                v.x = fmaxf(v.x, 0.f);
                v.y = fmaxf(v.y, 0.f);
                v.z = fmaxf(v.z, 0.f);
                v.w = fmaxf(v.w, 0.f);
            }
            reinterpret_cast<float4*>(out)[(size_t)d * NL + cid] = v;
        }
    }
}

// ---------------- launch ----------------
extern "C" void kernel_launch(void* const* d_in, const int* in_sizes, int n_in,
                              void* d_out, int out_size) {
    (void)in_sizes;
    (void)n_in;
    (void)out_size;
    const float* x    = (const float*)d_in[0];
    const int*   ei   = (const int*)d_in[1];
    const float* W0   = (const float*)d_in[2];
    const float* att0 = (const float*)d_in[3];
    const float* W1   = (const float*)d_in[4];
    const float* att1 = (const float*)d_in[5];
    float* out = (float*)d_out;

    void *p;
    float *h0, *h1, *h2, *adst, *asrc, *wself;
    int *rowptr, *cursor, *colp, *rankp, *bsum;
    cudaGetSymbolAddress(&p, g_h0);     h0 = (float*)p;
    cudaGetSymbolAddress(&p, g_h1);     h1 = (float*)p;
    cudaGetSymbolAddress(&p, g_h2);     h2 = (float*)p;
    cudaGetSymbolAddress(&p, g_adst);   adst = (float*)p;
    cudaGetSymbolAddress(&p, g_asrc);   asrc = (float*)p;
    cudaGetSymbolAddress(&p, g_wself);  wself = (float*)p;
    cudaGetSymbolAddress(&p, g_rowptr); rowptr = (int*)p;
    cudaGetSymbolAddress(&p, g_cursor); cursor = (int*)p;
    cudaGetSymbolAddress(&p, g_col);    colp = (int*)p;
    cudaGetSymbolAddress(&p, g_rank);   rankp = (int*)p;
    cudaGetSymbolAddress(&p, g_bsum);   bsum = (int*)p;

    cudaFuncSetAttribute(gemm1_mma_kernel,
                         cudaFuncAttributeMaxDynamicSharedMemorySize, SM_TOT);
    cudaFuncSetAttribute(gemm2_mma_kernel,
                         cudaFuncAttributeMaxDynamicSharedMemorySize, S2_TOT);

    const int TB = 256;
    int warp_blocks = (NN * 32 + TB - 1) / TB; // 12500

    // prep: convert W0/W1 once into pre-swizzled hi/lo buffers; reset bsum
    prep_w_kernel<<<11, TB>>>(W0, W1, bsum);

    // Layer-1 GEMM (M=64 tiles, 3 CTAs/SM) + histogram with rank capture
    gemm1_mma_kernel<<<GB1, TB, SM_TOT>>>(x, att0, h0, adst, asrc, wself, ei, cursor,
                                          rankp);

    // CSR finalize: one-kernel scan + atomic-free scatter
    scan_fused_kernel<<<NBLK, 1024>>>(cursor, rowptr, cursor, bsum);
    scatter_kernel<<<(EE / 4 + TB - 1) / TB, TB>>>(ei, rowptr, rankp, colp);

    // Layer 1 aggregation: 64ch, relu; also re-zeroes cursor for the next replay
    aggregate_kernel<64, true, false><<<warp_blocks, TB>>>(h0, adst, asrc, wself, rowptr,
                                                           colp, h1, cursor);

    // Layer 2: 64 -> 40 (warp mma.sync), then fused log_softmax aggregation
    gemm2_mma_kernel<<<GB2, TB, S2_TOT>>>(h1, att1, h2, adst, asrc, wself);
    aggregate_kernel<40, false, true><<<warp_blocks, TB>>>(h2, adst, asrc, wself, rowptr,
                                                           colp, out, nullptr);
}

// round 15
// speedup vs baseline: 1.0073x; 1.0073x over previous
#include <cuda_runtime.h>
#include <cuda_bf16.h>
#include <cstdint>

#define NN 100000
#define EE 1600000
#define NBLK 98          // ceil(NN/1024)
#define GB1 1563         // gemm1 blocks: ceil(NN/64)
#define GB2 782          // gemm2 blocks: ceil(NN/128)

#define SAS 272          // gemm1 smem row stride (bytes)
#define S2AS 144         // gemm2 smem row stride (bytes)

// ---------------- scratch ----------------
__device__ __align__(16) float g_h0[NN * 64];
__device__ __align__(16) float g_h1[NN * 64];
__device__ __align__(16) float g_h2[NN * 40];
__device__ float g_adst[NN];
__device__ float g_asrc[NN];
__device__ float g_wself[NN];
__device__ int   g_rowptr[NN + 1];
__device__ int   g_cursor[NN];   // zero at load; re-zeroed by agg1 tail each call
__device__ int   g_col[EE];
__device__ __align__(16) int g_rank[EE];  // per-edge rank within its dst (from hist)
__device__ int   g_bsum[128];    // re-zeroed by prep each call
// pre-swizzled W tiles (hi/lo bf16, exact smem layout incl. padding)
__device__ __align__(16) char g_w0h[64 * SAS];
__device__ __align__(16) char g_w0l[64 * SAS];
__device__ __align__(16) char g_w1h[40 * S2AS];
__device__ __align__(16) char g_w1l[40 * S2AS];

__device__ __forceinline__ float lrelu(float x) { return x < 0.f ? 0.2f * x : x; }

// ---------------- warp mma helper (sm_80+ baseline PTX; HMMA on Blackwell) ----------
__device__ __forceinline__ void mma16816(float* c, const uint32_t* a, const uint32_t* b) {
    asm volatile(
        "mma.sync.aligned.m16n8k16.row.col.f32.bf16.bf16.f32 "
        "{%0,%1,%2,%3}, {%4,%5,%6,%7}, {%8,%9}, {%0,%1,%2,%3};"
        : "+f"(c[0]), "+f"(c[1]), "+f"(c[2]), "+f"(c[3])
        : "r"(a[0]), "r"(a[1]), "r"(a[2]), "r"(a[3]), "r"(b[0]), "r"(b[1]));
}

// paired split-convert: hi = {bf16(y), bf16(x)}, lo = {bf16(y-hi.y), bf16(x-hi.x)}
__device__ __forceinline__ void cvt_split2(float x, float y, uint32_t& hi, uint32_t& lo) {
    asm("cvt.rn.bf16x2.f32 %0, %1, %2;" : "=r"(hi) : "f"(y), "f"(x));
    float lx = x - __uint_as_float(hi << 16);
    float ly = y - __uint_as_float(hi & 0xFFFF0000u);
    asm("cvt.rn.bf16x2.f32 %0, %1, %2;" : "=r"(lo) : "f"(ly), "f"(lx));
}

// ---------------- prep: convert W0/W1 once into pre-swizzled hi/lo buffers ----------
__global__ void __launch_bounds__(256) prep_w_kernel(const float* __restrict__ W0,
                                                     const float* __restrict__ W1,
                                                     int* __restrict__ bsum) {
    int tid = blockIdx.x * 256 + threadIdx.x;
    if (tid < 128) bsum[tid] = 0;
    if (tid < 64 * 32) {
        int r = tid >> 5, c4 = tid & 31;
        float4 v = reinterpret_cast<const float4*>(W0)[r * 32 + c4];
        uint2 hi, lo;
        cvt_split2(v.x, v.y, hi.x, lo.x);
        cvt_split2(v.z, v.w, hi.y, lo.y);
        int off = r * SAS + c4 * 8;
        *reinterpret_cast<uint2*>(g_w0h + off) = hi;
        *reinterpret_cast<uint2*>(g_w0l + off) = lo;
    }
    int t1 = tid - 64 * 32;
    if (t1 >= 0 && t1 < 40 * 16) {
        int r = t1 >> 4, c4 = t1 & 15;
        float4 v = reinterpret_cast<const float4*>(W1)[r * 16 + c4];
        uint2 hi, lo;
        cvt_split2(v.x, v.y, hi.x, lo.x);
        cvt_split2(v.z, v.w, hi.y, lo.y);
        int off = r * S2AS + c4 * 8;
        *reinterpret_cast<uint2*>(g_w1h + off) = hi;
        *reinterpret_cast<uint2*>(g_w1l + off) = lo;
    }
}

// ---------------- layer-1 GEMM: M=64 tiles, 3 CTAs/SM, bf16 2-term split ------------
// Histogram atomics issue at CTA start; their RETURNS (edge ranks) are held in
// registers and stored only after the MMA mainloop, so the ~318cy ATOMG round trip
// is fully hidden under smem fill + 24 HMMA steps.
#define SM_ATT 0
#define SM_PD  512
#define SM_PS  768
#define SM_AHI 1024
#define SM_ALO (SM_AHI + 64 * SAS)
#define SM_BHI (SM_ALO + 64 * SAS)
#define SM_BLO (SM_BHI + 64 * SAS)
#define SM_TOT (SM_BLO + 64 * SAS)

__global__ void __launch_bounds__(256) gemm1_mma_kernel(
    const float* __restrict__ A, const float* __restrict__ att, float* __restrict__ C,
    float* __restrict__ adst, float* __restrict__ asrc, float* __restrict__ wself,
    const int* __restrict__ ei, int* __restrict__ deg, int* __restrict__ rank) {
    extern __shared__ char ds[];
    int tid = threadIdx.x;
    int row0 = blockIdx.x * 64;

    // issue histogram atomics early; returns consumed at the very end of the kernel
    int t4 = blockIdx.x * 256 + tid;
    bool have_edges = (t4 < EE / 4);
    int4 r4;
    if (have_edges) {
        int4 d4 = reinterpret_cast<const int4*>(ei + EE)[t4];
        r4.x = atomicAdd(deg + d4.x, 1);
        r4.y = atomicAdd(deg + d4.y, 1);
        r4.z = atomicAdd(deg + d4.z, 1);
        r4.w = atomicAdd(deg + d4.w, 1);
    }

    float* att_s = reinterpret_cast<float*>(ds + SM_ATT);
    float* spd = reinterpret_cast<float*>(ds + SM_PD);
    float* sps = reinterpret_cast<float*>(ds + SM_PS);
    if (tid < 128) att_s[tid] = __ldg(att + tid);
    if (tid < 64) {
        spd[tid] = 0.f;
        sps[tid] = 0.f;
    }

    // A tile: 64x128 fp32 -> bf16 hi/lo via paired cvt
    const float4* A4 = reinterpret_cast<const float4*>(A);
    for (int idx = tid; idx < 64 * 32; idx += 256) {
        int r = idx >> 5, c4 = idx & 31;
        float4 v = make_float4(0.f, 0.f, 0.f, 0.f);
        int gn = row0 + r;
        if (gn < NN) v = A4[gn * 32 + c4];
        uint2 hi, lo;
        cvt_split2(v.x, v.y, hi.x, lo.x);
        cvt_split2(v.z, v.w, hi.y, lo.y);
        int off = r * SAS + c4 * 8;
        *reinterpret_cast<uint2*>(ds + SM_AHI + off) = hi;
        *reinterpret_cast<uint2*>(ds + SM_ALO + off) = lo;
    }
    // B tile: plain uint4 copy of pre-swizzled W0 (L2-resident)
    for (int idx = tid; idx < 64 * SAS / 16; idx += 256) {
        reinterpret_cast<uint4*>(ds + SM_BHI)[idx] =
            reinterpret_cast<const uint4*>(g_w0h)[idx];
        reinterpret_cast<uint4*>(ds + SM_BLO)[idx] =
            reinterpret_cast<const uint4*>(g_w0l)[idx];
    }
    __syncthreads();

    int wid = tid >> 5;
    int lane = tid & 31;
    int wm = wid & 3;
    int wn = wid >> 2;
    int g = lane >> 2;
    int t = lane & 3;

    float c[4][4];
#pragma unroll
    for (int nt = 0; nt < 4; ++nt)
#pragma unroll
        for (int q = 0; q < 4; ++q) c[nt][q] = 0.f;

    int arow = (wm * 16 + g) * SAS + t * 4;
    int brow = (wn * 32 + g) * SAS + t * 4;

#pragma unroll
    for (int kk = 0; kk < 8; ++kk) {
        int kb = kk * 32;
        uint32_t aH[4], aL[4], bH[4][2], bL[4][2];
        int base = arow + kb;
        aH[0] = *reinterpret_cast<const uint32_t*>(ds + SM_AHI + base);
        aH[1] = *reinterpret_cast<const uint32_t*>(ds + SM_AHI + base + 8 * SAS);
        aH[2] = *reinterpret_cast<const uint32_t*>(ds + SM_AHI + base + 16);
        aH[3] = *reinterpret_cast<const uint32_t*>(ds + SM_AHI + base + 8 * SAS + 16);
        aL[0] = *reinterpret_cast<const uint32_t*>(ds + SM_ALO + base);
        aL[1] = *reinterpret_cast<const uint32_t*>(ds + SM_ALO + base + 8 * SAS);
        aL[2] = *reinterpret_cast<const uint32_t*>(ds + SM_ALO + base + 16);
        aL[3] = *reinterpret_cast<const uint32_t*>(ds + SM_ALO + base + 8 * SAS + 16);
#pragma unroll
        for (int nt = 0; nt < 4; ++nt) {
            int bb = brow + nt * 8 * SAS + kb;
            bH[nt][0] = *reinterpret_cast<const uint32_t*>(ds + SM_BHI + bb);
            bH[nt][1] = *reinterpret_cast<const uint32_t*>(ds + SM_BHI + bb + 16);
            bL[nt][0] = *reinterpret_cast<const uint32_t*>(ds + SM_BLO + bb);
            bL[nt][1] = *reinterpret_cast<const uint32_t*>(ds + SM_BLO + bb + 16);
        }
#pragma unroll
        for (int nt = 0; nt < 4; ++nt) {
            mma16816(c[nt], aH, bH[nt]);
            mma16816(c[nt], aH, bL[nt]);
            mma16816(c[nt], aL, bH[nt]);
        }
    }

    // rank store: atomic returns arrived long ago; store is now latency-free
    if (have_edges) reinterpret_cast<int4*>(rank)[t4] = r4;

    // epilogue: store C + alpha dot partials (quad reduce -> smem atomics)
    int lr0 = wm * 16 + g, lr1 = lr0 + 8;
    int gn0 = row0 + lr0, gn1 = row0 + lr1;
    float pd0 = 0.f, ps0 = 0.f, pd1 = 0.f, ps1 = 0.f;
#pragma unroll
    for (int nt = 0; nt < 4; ++nt) {
        int col = wn * 32 + nt * 8 + 2 * t;
        float c0 = c[nt][0], c1 = c[nt][1], c2 = c[nt][2], c3 = c[nt][3];
        pd0 += c0 * att_s[col] + c1 * att_s[col + 1];
        ps0 += c0 * att_s[64 + col] + c1 * att_s[64 + col + 1];
        pd1 += c2 * att_s[col] + c3 * att_s[col + 1];
        ps1 += c2 * att_s[64 + col] + c3 * att_s[64 + col + 1];
        if (gn0 < NN)
            *reinterpret_cast<float2*>(C + (size_t)gn0 * 64 + col) = make_float2(c0, c1);
        if (gn1 < NN)
            *reinterpret_cast<float2*>(C + (size_t)gn1 * 64 + col) = make_float2(c2, c3);
    }
#pragma unroll
    for (int o = 1; o <= 2; o <<= 1) {
        pd0 += __shfl_down_sync(0xffffffffu, pd0, o);
        ps0 += __shfl_down_sync(0xffffffffu, ps0, o);
        pd1 += __shfl_down_sync(0xffffffffu, pd1, o);
        ps1 += __shfl_down_sync(0xffffffffu, ps1, o);
    }
    if (t == 0) {
        atomicAdd(spd + lr0, pd0);
        atomicAdd(sps + lr0, ps0);
        atomicAdd(spd + lr1, pd1);
        atomicAdd(sps + lr1, ps1);
    }
    __syncthreads();
    if (tid < 64) {
        int gn = row0 + tid;
        if (gn < NN) {
            float pd = spd[tid], ps = sps[tid];
            adst[gn] = pd;
            asrc[gn] = ps;
            wself[gn] = __expf(lrelu(pd + ps));
        }
    }
}

// ---------------- layer-2 GEMM (warp mma, bf16 2-term split, M=128 N=40 K=64) --------
#define S2_ATT 0
#define S2_AHI 512
#define S2_ALO (S2_AHI + 128 * S2AS)
#define S2_BHI (S2_ALO + 128 * S2AS)
#define S2_BLO (S2_BHI + 40 * S2AS)
#define S2_TOT (S2_BLO + 40 * S2AS)

__global__ void __launch_bounds__(256) gemm2_mma_kernel(
    const float* __restrict__ A, const float* __restrict__ att, float* __restrict__ C,
    float* __restrict__ adst, float* __restrict__ asrc, float* __restrict__ wself) {
    extern __shared__ char ds[];
    int tid = threadIdx.x;
    int row0 = blockIdx.x * 128;

    float* att_s = reinterpret_cast<float*>(ds + S2_ATT);
    if (tid < 80) att_s[tid] = __ldg(att + tid);

    const float4* A4 = reinterpret_cast<const float4*>(A);
    for (int idx = tid; idx < 128 * 16; idx += 256) {
        int r = idx >> 4, c4 = idx & 15;
        float4 v = make_float4(0.f, 0.f, 0.f, 0.f);
        int gn = row0 + r;
        if (gn < NN) v = A4[gn * 16 + c4];
        uint2 hi, lo;
        cvt_split2(v.x, v.y, hi.x, lo.x);
        cvt_split2(v.z, v.w, hi.y, lo.y);
        int off = r * S2AS + c4 * 8;
        *reinterpret_cast<uint2*>(ds + S2_AHI + off) = hi;
        *reinterpret_cast<uint2*>(ds + S2_ALO + off) = lo;
    }
    for (int idx = tid; idx < 40 * S2AS / 16; idx += 256) {
        reinterpret_cast<uint4*>(ds + S2_BHI)[idx] =
            reinterpret_cast<const uint4*>(g_w1h)[idx];
        reinterpret_cast<uint4*>(ds + S2_BLO)[idx] =
            reinterpret_cast<const uint4*>(g_w1l)[idx];
    }
    __syncthreads();

    int wid = tid >> 5;
    int lane = tid & 31;
    int g = lane >> 2;
    int t = lane & 3;

    float c[5][4];
#pragma unroll
    for (int nt = 0; nt < 5; ++nt)
#pragma unroll
        for (int q = 0; q < 4; ++q) c[nt][q] = 0.f;

    int arow = (wid * 16 + g) * S2AS + t * 4;
    int brow = g * S2AS + t * 4;

#pragma unroll
    for (int kk = 0; kk < 4; ++kk) {
        int kb = kk * 32;
        uint32_t aH[4], aL[4], bH[5][2], bL[5][2];
        int base = arow + kb;
        aH[0] = *reinterpret_cast<const uint32_t*>(ds + S2_AHI + base);
        aH[1] = *reinterpret_cast<const uint32_t*>(ds + S2_AHI + base + 8 * S2AS);
        aH[2] = *reinterpret_cast<const uint32_t*>(ds + S2_AHI + base + 16);
        aH[3] = *reinterpret_cast<const uint32_t*>(ds + S2_AHI + base + 8 * S2AS + 16);
        aL[0] = *reinterpret_cast<const uint32_t*>(ds + S2_ALO + base);
        aL[1] = *reinterpret_cast<const uint32_t*>(ds + S2_ALO + base + 8 * S2AS);
        aL[2] = *reinterpret_cast<const uint32_t*>(ds + S2_ALO + base + 16);
        aL[3] = *reinterpret_cast<const uint32_t*>(ds + S2_ALO + base + 8 * S2AS + 16);
#pragma unroll
        for (int nt = 0; nt < 5; ++nt) {
            int bb = brow + nt * 8 * S2AS + kb;
            bH[nt][0] = *reinterpret_cast<const uint32_t*>(ds + S2_BHI + bb);
            bH[nt][1] = *reinterpret_cast<const uint32_t*>(ds + S2_BHI + bb + 16);
            bL[nt][0] = *reinterpret_cast<const uint32_t*>(ds + S2_BLO + bb);
            bL[nt][1] = *reinterpret_cast<const uint32_t*>(ds + S2_BLO + bb + 16);
        }
#pragma unroll
        for (int nt = 0; nt < 5; ++nt) {
            mma16816(c[nt], aH, bH[nt]);
            mma16816(c[nt], aH, bL[nt]);
            mma16816(c[nt], aL, bH[nt]);
        }
    }

    int lr0 = wid * 16 + g, lr1 = lr0 + 8;
    int gn0 = row0 + lr0, gn1 = row0 + lr1;
    float pd0 = 0.f, ps0 = 0.f, pd1 = 0.f, ps1 = 0.f;
#pragma unroll
    for (int nt = 0; nt < 5; ++nt) {
        int col = nt * 8 + 2 * t;
        float c0 = c[nt][0], c1 = c[nt][1], c2 = c[nt][2], c3 = c[nt][3];
        pd0 += c0 * att_s[col] + c1 * att_s[col + 1];
        ps0 += c0 * att_s[40 + col] + c1 * att_s[40 + col + 1];
        pd1 += c2 * att_s[col] + c3 * att_s[col + 1];
        ps1 += c2 * att_s[40 + col] + c3 * att_s[40 + col + 1];
        if (gn0 < NN)
            *reinterpret_cast<float2*>(C + (size_t)gn0 * 40 + col) = make_float2(c0, c1);
        if (gn1 < NN)
            *reinterpret_cast<float2*>(C + (size_t)gn1 * 40 + col) = make_float2(c2, c3);
    }
#pragma unroll
    for (int o = 1; o <= 2; o <<= 1) {
        pd0 += __shfl_down_sync(0xffffffffu, pd0, o);
        ps0 += __shfl_down_sync(0xffffffffu, ps0, o);
        pd1 += __shfl_down_sync(0xffffffffu, pd1, o);
        ps1 += __shfl_down_sync(0xffffffffu, ps1, o);
    }
    if (t == 0) {
        if (gn0 < NN) {
            adst[gn0] = pd0;
            asrc[gn0] = ps0;
            wself[gn0] = __expf(lrelu(pd0 + ps0));
        }
        if (gn1 < NN) {
            adst[gn1] = pd1;
            asrc[gn1] = ps1;
            wself[gn1] = __expf(lrelu(pd1 + ps1));
        }
    }
}

// ---------------- CSR build: fused scan with decoupled lookback ----------------
#define SCAN_FLAG 0x40000000

__global__ void __launch_bounds__(1024) scan_fused_kernel(
    const int* __restrict__ deg, int* __restrict__ rowp, int* __restrict__ cursor,
    int* __restrict__ partial) {
    __shared__ int wsum[32];
    __shared__ int s_off;
    int tid = threadIdx.x, b = blockIdx.x;
    int lane = tid & 31, w = tid >> 5;
    int i = b * 1024 + tid;
    int v = (i < NN) ? deg[i] : 0;

    int x = v;
#pragma unroll
    for (int o = 1; o < 32; o <<= 1) {
        int y = __shfl_up_sync(0xffffffffu, x, o);
        if (lane >= o) x += y;
    }
    if (lane == 31) wsum[w] = x;
    __syncthreads();
    if (w == 0) {
        int s = wsum[lane];
#pragma unroll
        for (int o = 1; o < 32; o <<= 1) {
            int y = __shfl_up_sync(0xffffffffu, s, o);
            if (lane >= o) s += y;
        }
        wsum[lane] = s;
        if (lane == 31) {
            atomicExch(partial + b, s | SCAN_FLAG);
        }
        int acc = 0;
        for (int j = lane; j < b; j += 32) {
            int p;
            do {
                p = *((volatile int*)(partial + j));
            } while (!(p & SCAN_FLAG));
            acc += p & (SCAN_FLAG - 1);
        }
#pragma unroll
        for (int o = 16; o; o >>= 1) acc += __shfl_xor_sync(0xffffffffu, acc, o);
        if (lane == 0) s_off = acc;
    }
    __syncthreads();
    int excl = ((w == 0) ? 0 : wsum[w - 1]) + x - v + s_off;
    if (i < NN) {
        rowp[i] = excl;
        cursor[i] = excl;
    }
    if (i == 0) rowp[NN] = EE;
}

// ---------------- scatter: atomic-free deterministic slots ----------------
__global__ void __launch_bounds__(256) scatter_kernel(
    const int* __restrict__ ei, const int* __restrict__ rowp,
    const int* __restrict__ rank, int* __restrict__ col) {
    int t = blockIdx.x * 256 + threadIdx.x;
    if (t < EE / 4) {
        int4 s4 = reinterpret_cast<const int4*>(ei)[t];
        int4 d4 = reinterpret_cast<const int4*>(ei + EE)[t];
        int4 r4 = reinterpret_cast<const int4*>(rank)[t];
        col[__ldg(rowp + d4.x) + r4.x] = s4.x;
        col[__ldg(rowp + d4.y) + r4.y] = s4.y;
        col[__ldg(rowp + d4.z) + r4.z] = s4.z;
        col[__ldg(rowp + d4.w) + r4.w] = s4.w;
    }
}

// ---------------- aggregation: shfl-free gather, inline edge weights ----------------
// czero (nullable): buffer to zero for the next replay (cursor, consumed by hist).
template <int CH, bool RELU, bool LSM>
__global__ void aggregate_kernel(const float* __restrict__ h, const float* __restrict__ adst,
                                 const float* __restrict__ asrc,
                                 const float* __restrict__ wself,
                                 const int* __restrict__ rowp, const int* __restrict__ col,
                                 float* __restrict__ out, int* __restrict__ czero) {
    constexpr int NL = CH / 4;    // 16 or 10
    constexpr int NG = 32 / NL;   // 2 or 3

    int gtid = blockIdx.x * blockDim.x + threadIdx.x;
    if (czero != nullptr && gtid < NN) czero[gtid] = 0;

    int d = gtid >> 5;
    int lane = threadIdx.x & 31;
    if (d >= NN) return;

    int rs = __ldg(rowp + d), re = __ldg(rowp + d + 1);
    float ad = __ldg(adst + d);

    int group = lane / NL;
    if (group >= NG) group = NG - 1;
    int cid = lane - group * NL;
    if (cid >= NL) cid -= NL;

    const float4* __restrict__ h4 = reinterpret_cast<const float4*>(h);

    float4 acc = make_float4(0.f, 0.f, 0.f, 0.f);
    float psum = 0.f;

    for (int j = rs + group; j < re; j += NG) {
        int s = __ldg(col + j);
        float e = __expf(lrelu(ad + __ldg(asrc + s)));
        float4 hv = __ldg(h4 + s * NL + cid);
        psum += e;
        acc.x += e * hv.x;
        acc.y += e * hv.y;
        acc.z += e * hv.z;
        acc.w += e * hv.w;
    }

    float es = __ldg(wself + d);

    if (group == 0 && lane < NL) {
        float4 hv = __ldg(h4 + d * NL + cid);
        acc.x += es * hv.x;
        acc.y += es * hv.y;
        acc.z += es * hv.z;
        acc.w += es * hv.w;
    }

#pragma unroll
    for (int g = 1; g < NG; ++g) {
        int sl = lane + g * NL;
        float px = __shfl_sync(0xffffffffu, acc.x, sl & 31);
        float py = __shfl_sync(0xffffffffu, acc.y, sl & 31);
        float pz = __shfl_sync(0xffffffffu, acc.z, sl & 31);
        float pw = __shfl_sync(0xffffffffu, acc.w, sl & 31);
        float pp = __shfl_sync(0xffffffffu, psum, g * NL);
        if (lane < NL) {
            acc.x += px;
            acc.y += py;
            acc.z += pz;
            acc.w += pw;
        }
        psum = (lane == 0) ? psum + pp : psum;
    }
    psum = __shfl_sync(0xffffffffu, psum, 0) + es;

    float4 v = make_float4(0.f, 0.f, 0.f, 0.f);
    if (lane < NL) {
        float inv = 1.0f / psum;
        v.x = acc.x * inv;
        v.y = acc.y * inv;
        v.z = acc.z * inv;
        v.w = acc.w * inv;
    }

    if (LSM) {
        float vm = -1e30f;
        if (lane < NL) vm = fmaxf(fmaxf(v.x, v.y), fmaxf(v.z, v.w));
#pragma unroll
        for (int o = 16; o; o >>= 1) vm = fmaxf(vm, __shfl_xor_sync(0xffffffffu, vm, o));
        float se = 0.f;
        if (lane < NL)
            se = __expf(v.x - vm) + __expf(v.y - vm) + __expf(v.z - vm) + __expf(v.w - vm);
#pragma unroll
        for (int o = 16; o; o >>= 1) se += __shfl_xor_sync(0xffffffffu, se, o);
        float l = vm + logf(se);
        if (lane < NL) {
            v.x -= l;
            v.y -= l;
            v.z -= l;
            v.w -= l;
            reinterpret_cast<float4*>(out)[(size_t)d * NL + cid] = v;
        }
    } else {
        if (lane < NL) {
            if (RELU) {
                v.x = fmaxf(v.x, 0.f);
                v.y = fmaxf(v.y, 0.f);
                v.z = fmaxf(v.z, 0.f);
                v.w = fmaxf(v.w, 0.f);
            }
            reinterpret_cast<float4*>(out)[(size_t)d * NL + cid] = v;
        }
    }
}

// ---------------- launch ----------------
extern "C" void kernel_launch(void* const* d_in, const int* in_sizes, int n_in,
                              void* d_out, int out_size) {
    (void)in_sizes;
    (void)n_in;
    (void)out_size;
    const float* x    = (const float*)d_in[0];
    const int*   ei   = (const int*)d_in[1];
    const float* W0   = (const float*)d_in[2];
    const float* att0 = (const float*)d_in[3];
    const float* W1   = (const float*)d_in[4];
    const float* att1 = (const float*)d_in[5];
    float* out = (float*)d_out;

    void *p;
    float *h0, *h1, *h2, *adst, *asrc, *wself;
    int *rowptr, *cursor, *colp, *rankp, *bsum;
    cudaGetSymbolAddress(&p, g_h0);     h0 = (float*)p;
    cudaGetSymbolAddress(&p, g_h1);     h1 = (float*)p;
    cudaGetSymbolAddress(&p, g_h2);     h2 = (float*)p;
    cudaGetSymbolAddress(&p, g_adst);   adst = (float*)p;
    cudaGetSymbolAddress(&p, g_asrc);   asrc = (float*)p;
    cudaGetSymbolAddress(&p, g_wself);  wself = (float*)p;
    cudaGetSymbolAddress(&p, g_rowptr); rowptr = (int*)p;
    cudaGetSymbolAddress(&p, g_cursor); cursor = (int*)p;
    cudaGetSymbolAddress(&p, g_col);    colp = (int*)p;
    cudaGetSymbolAddress(&p, g_rank);   rankp = (int*)p;
    cudaGetSymbolAddress(&p, g_bsum);   bsum = (int*)p;

    cudaFuncSetAttribute(gemm1_mma_kernel,
                         cudaFuncAttributeMaxDynamicSharedMemorySize, SM_TOT);
    cudaFuncSetAttribute(gemm2_mma_kernel,
                         cudaFuncAttributeMaxDynamicSharedMemorySize, S2_TOT);

    const int TB = 256;
    int warp_blocks = (NN * 32 + TB - 1) / TB; // 12500

    // prep: convert W0/W1 once into pre-swizzled hi/lo buffers; reset bsum
    prep_w_kernel<<<11, TB>>>(W0, W1, bsum);

    // Layer-1 GEMM (M=64 tiles, 3 CTAs/SM) + histogram; rank stores deferred past MMA
    gemm1_mma_kernel<<<GB1, TB, SM_TOT>>>(x, att0, h0, adst, asrc, wself, ei, cursor,
                                          rankp);

    // CSR finalize: one-kernel scan + atomic-free scatter
    scan_fused_kernel<<<NBLK, 1024>>>(cursor, rowptr, cursor, bsum);
    scatter_kernel<<<(EE / 4 + TB - 1) / TB, TB>>>(ei, rowptr, rankp, colp);

    // Layer 1 aggregation: 64ch, relu; also re-zeroes cursor for the next replay
    aggregate_kernel<64, true, false><<<warp_blocks, TB>>>(h0, adst, asrc, wself, rowptr,
                                                           colp, h1, cursor);

    // Layer 2: 64 -> 40 (warp mma.sync), then fused log_softmax aggregation
    gemm2_mma_kernel<<<GB2, TB, S2_TOT>>>(h1, att1, h2, adst, asrc, wself);
    aggregate_kernel<40, false, true><<<warp_blocks, TB>>>(h2, adst, asrc, wself, rowptr,
                                                           colp, out, nullptr);
}

// round 16
// speedup vs baseline: 1.0423x; 1.0347x over previous
#include <cuda_runtime.h>
#include <cuda_bf16.h>
#include <cstdint>

#define NN 100000
#define EE 1600000
#define NBLK 98          // ceil(NN/1024)
#define GB1 1563         // gemm1 blocks: ceil(NN/64)
#define GB2 782          // gemm2 blocks: ceil(NN/128)

#define SAS 272          // gemm1 smem row stride (bytes)
#define S2AS 144         // gemm2 smem row stride (bytes)

// ---------------- scratch ----------------
__device__ __align__(16) float g_h0[NN * 64];
__device__ __align__(16) float g_h1[NN * 64];
__device__ __align__(16) float g_h2[NN * 40];
__device__ float g_adst[NN];
__device__ float g_asrc[NN];
__device__ float g_wself[NN];
__device__ int   g_rowptr[NN + 1];
__device__ int   g_cursor[NN];   // zero at load; re-zeroed by agg1 tail each call
__device__ int   g_col[EE];
__device__ int   g_bsum[128];    // re-zeroed by prep each call
// pre-swizzled W tiles (hi/lo bf16, exact smem layout incl. padding)
__device__ __align__(16) char g_w0h[64 * SAS];
__device__ __align__(16) char g_w0l[64 * SAS];
__device__ __align__(16) char g_w1h[40 * S2AS];
__device__ __align__(16) char g_w1l[40 * S2AS];

__device__ __forceinline__ float lrelu(float x) { return x < 0.f ? 0.2f * x : x; }

// ---------------- warp mma helper (sm_80+ baseline PTX; HMMA on Blackwell) ----------
__device__ __forceinline__ void mma16816(float* c, const uint32_t* a, const uint32_t* b) {
    asm volatile(
        "mma.sync.aligned.m16n8k16.row.col.f32.bf16.bf16.f32 "
        "{%0,%1,%2,%3}, {%4,%5,%6,%7}, {%8,%9}, {%0,%1,%2,%3};"
        : "+f"(c[0]), "+f"(c[1]), "+f"(c[2]), "+f"(c[3])
        : "r"(a[0]), "r"(a[1]), "r"(a[2]), "r"(a[3]), "r"(b[0]), "r"(b[1]));
}

// paired split-convert: hi = {bf16(y), bf16(x)}, lo = {bf16(y-hi.y), bf16(x-hi.x)}
__device__ __forceinline__ void cvt_split2(float x, float y, uint32_t& hi, uint32_t& lo) {
    asm("cvt.rn.bf16x2.f32 %0, %1, %2;" : "=r"(hi) : "f"(y), "f"(x));
    float lx = x - __uint_as_float(hi << 16);
    float ly = y - __uint_as_float(hi & 0xFFFF0000u);
    asm("cvt.rn.bf16x2.f32 %0, %1, %2;" : "=r"(lo) : "f"(ly), "f"(lx));
}

// ---------------- prep: convert W0/W1 once into pre-swizzled hi/lo buffers ----------
__global__ void __launch_bounds__(256) prep_w_kernel(const float* __restrict__ W0,
                                                     const float* __restrict__ W1,
                                                     int* __restrict__ bsum) {
    int tid = blockIdx.x * 256 + threadIdx.x;
    if (tid < 128) bsum[tid] = 0;
    if (tid < 64 * 32) {
        int r = tid >> 5, c4 = tid & 31;
        float4 v = reinterpret_cast<const float4*>(W0)[r * 32 + c4];
        uint2 hi, lo;
        cvt_split2(v.x, v.y, hi.x, lo.x);
        cvt_split2(v.z, v.w, hi.y, lo.y);
        int off = r * SAS + c4 * 8;
        *reinterpret_cast<uint2*>(g_w0h + off) = hi;
        *reinterpret_cast<uint2*>(g_w0l + off) = lo;
    }
    int t1 = tid - 64 * 32;
    if (t1 >= 0 && t1 < 40 * 16) {
        int r = t1 >> 4, c4 = t1 & 15;
        float4 v = reinterpret_cast<const float4*>(W1)[r * 16 + c4];
        uint2 hi, lo;
        cvt_split2(v.x, v.y, hi.x, lo.x);
        cvt_split2(v.z, v.w, hi.y, lo.y);
        int off = r * S2AS + c4 * 8;
        *reinterpret_cast<uint2*>(g_w1h + off) = hi;
        *reinterpret_cast<uint2*>(g_w1l + off) = lo;
    }
}

// ---------------- layer-1 GEMM: M=64 tiles, 3 CTAs/SM, bf16 2-term split ------------
// Embedded histogram (fire-and-forget RED, no return) overlaps the prologue.
#define SM_ATT 0
#define SM_PD  512
#define SM_PS  768
#define SM_AHI 1024
#define SM_ALO (SM_AHI + 64 * SAS)
#define SM_BHI (SM_ALO + 64 * SAS)
#define SM_BLO (SM_BHI + 64 * SAS)
#define SM_TOT (SM_BLO + 64 * SAS)

__global__ void __launch_bounds__(256) gemm1_mma_kernel(
    const float* __restrict__ A, const float* __restrict__ att, float* __restrict__ C,
    float* __restrict__ adst, float* __restrict__ asrc, float* __restrict__ wself,
    const int* __restrict__ ei, int* __restrict__ deg) {
    extern __shared__ char ds[];
    int tid = threadIdx.x;
    int row0 = blockIdx.x * 64;

    // embedded degree histogram: 1024 edges per CTA (fire-and-forget RED)
    {
        int t4 = blockIdx.x * 256 + tid;
        if (t4 < EE / 4) {
            int4 d4 = reinterpret_cast<const int4*>(ei + EE)[t4];
            atomicAdd(deg + d4.x, 1);
            atomicAdd(deg + d4.y, 1);
            atomicAdd(deg + d4.z, 1);
            atomicAdd(deg + d4.w, 1);
        }
    }

    float* att_s = reinterpret_cast<float*>(ds + SM_ATT);
    float* spd = reinterpret_cast<float*>(ds + SM_PD);
    float* sps = reinterpret_cast<float*>(ds + SM_PS);
    if (tid < 128) att_s[tid] = __ldg(att + tid);
    if (tid < 64) {
        spd[tid] = 0.f;
        sps[tid] = 0.f;
    }

    // A tile: 64x128 fp32 -> bf16 hi/lo via paired cvt
    const float4* A4 = reinterpret_cast<const float4*>(A);
    for (int idx = tid; idx < 64 * 32; idx += 256) {
        int r = idx >> 5, c4 = idx & 31;
        float4 v = make_float4(0.f, 0.f, 0.f, 0.f);
        int gn = row0 + r;
        if (gn < NN) v = A4[gn * 32 + c4];
        uint2 hi, lo;
        cvt_split2(v.x, v.y, hi.x, lo.x);
        cvt_split2(v.z, v.w, hi.y, lo.y);
        int off = r * SAS + c4 * 8;
        *reinterpret_cast<uint2*>(ds + SM_AHI + off) = hi;
        *reinterpret_cast<uint2*>(ds + SM_ALO + off) = lo;
    }
    // B tile: plain uint4 copy of pre-swizzled W0 (L2-resident)
    for (int idx = tid; idx < 64 * SAS / 16; idx += 256) {
        reinterpret_cast<uint4*>(ds + SM_BHI)[idx] =
            reinterpret_cast<const uint4*>(g_w0h)[idx];
        reinterpret_cast<uint4*>(ds + SM_BLO)[idx] =
            reinterpret_cast<const uint4*>(g_w0l)[idx];
    }
    __syncthreads();

    int wid = tid >> 5;
    int lane = tid & 31;
    int wm = wid & 3;
    int wn = wid >> 2;
    int g = lane >> 2;
    int t = lane & 3;

    float c[4][4];
#pragma unroll
    for (int nt = 0; nt < 4; ++nt)
#pragma unroll
        for (int q = 0; q < 4; ++q) c[nt][q] = 0.f;

    int arow = (wm * 16 + g) * SAS + t * 4;
    int brow = (wn * 32 + g) * SAS + t * 4;

#pragma unroll
    for (int kk = 0; kk < 8; ++kk) {
        int kb = kk * 32;
        uint32_t aH[4], aL[4], bH[4][2], bL[4][2];
        int base = arow + kb;
        aH[0] = *reinterpret_cast<const uint32_t*>(ds + SM_AHI + base);
        aH[1] = *reinterpret_cast<const uint32_t*>(ds + SM_AHI + base + 8 * SAS);
        aH[2] = *reinterpret_cast<const uint32_t*>(ds + SM_AHI + base + 16);
        aH[3] = *reinterpret_cast<const uint32_t*>(ds + SM_AHI + base + 8 * SAS + 16);
        aL[0] = *reinterpret_cast<const uint32_t*>(ds + SM_ALO + base);
        aL[1] = *reinterpret_cast<const uint32_t*>(ds + SM_ALO + base + 8 * SAS);
        aL[2] = *reinterpret_cast<const uint32_t*>(ds + SM_ALO + base + 16);
        aL[3] = *reinterpret_cast<const uint32_t*>(ds + SM_ALO + base + 8 * SAS + 16);
#pragma unroll
        for (int nt = 0; nt < 4; ++nt) {
            int bb = brow + nt * 8 * SAS + kb;
            bH[nt][0] = *reinterpret_cast<const uint32_t*>(ds + SM_BHI + bb);
            bH[nt][1] = *reinterpret_cast<const uint32_t*>(ds + SM_BHI + bb + 16);
            bL[nt][0] = *reinterpret_cast<const uint32_t*>(ds + SM_BLO + bb);
            bL[nt][1] = *reinterpret_cast<const uint32_t*>(ds + SM_BLO + bb + 16);
        }
#pragma unroll
        for (int nt = 0; nt < 4; ++nt) {
            mma16816(c[nt], aH, bH[nt]);
            mma16816(c[nt], aH, bL[nt]);
            mma16816(c[nt], aL, bH[nt]);
        }
    }

    // epilogue: store C + alpha dot partials (quad reduce -> smem atomics)
    int lr0 = wm * 16 + g, lr1 = lr0 + 8;
    int gn0 = row0 + lr0, gn1 = row0 + lr1;
    float pd0 = 0.f, ps0 = 0.f, pd1 = 0.f, ps1 = 0.f;
#pragma unroll
    for (int nt = 0; nt < 4; ++nt) {
        int col = wn * 32 + nt * 8 + 2 * t;
        float c0 = c[nt][0], c1 = c[nt][1], c2 = c[nt][2], c3 = c[nt][3];
        pd0 += c0 * att_s[col] + c1 * att_s[col + 1];
        ps0 += c0 * att_s[64 + col] + c1 * att_s[64 + col + 1];
        pd1 += c2 * att_s[col] + c3 * att_s[col + 1];
        ps1 += c2 * att_s[64 + col] + c3 * att_s[64 + col + 1];
        if (gn0 < NN)
            *reinterpret_cast<float2*>(C + (size_t)gn0 * 64 + col) = make_float2(c0, c1);
        if (gn1 < NN)
            *reinterpret_cast<float2*>(C + (size_t)gn1 * 64 + col) = make_float2(c2, c3);
    }
#pragma unroll
    for (int o = 1; o <= 2; o <<= 1) {
        pd0 += __shfl_down_sync(0xffffffffu, pd0, o);
        ps0 += __shfl_down_sync(0xffffffffu, ps0, o);
        pd1 += __shfl_down_sync(0xffffffffu, pd1, o);
        ps1 += __shfl_down_sync(0xffffffffu, ps1, o);
    }
    if (t == 0) {
        atomicAdd(spd + lr0, pd0);
        atomicAdd(sps + lr0, ps0);
        atomicAdd(spd + lr1, pd1);
        atomicAdd(sps + lr1, ps1);
    }
    __syncthreads();
    if (tid < 64) {
        int gn = row0 + tid;
        if (gn < NN) {
            float pd = spd[tid], ps = sps[tid];
            adst[gn] = pd;
            asrc[gn] = ps;
            wself[gn] = __expf(lrelu(pd + ps));
        }
    }
}

// ---------------- layer-2 GEMM (warp mma, bf16 2-term split, M=128 N=40 K=64) --------
#define S2_ATT 0
#define S2_AHI 512
#define S2_ALO (S2_AHI + 128 * S2AS)
#define S2_BHI (S2_ALO + 128 * S2AS)
#define S2_BLO (S2_BHI + 40 * S2AS)
#define S2_TOT (S2_BLO + 40 * S2AS)

__global__ void __launch_bounds__(256) gemm2_mma_kernel(
    const float* __restrict__ A, const float* __restrict__ att, float* __restrict__ C,
    float* __restrict__ adst, float* __restrict__ asrc, float* __restrict__ wself) {
    extern __shared__ char ds[];
    int tid = threadIdx.x;
    int row0 = blockIdx.x * 128;

    float* att_s = reinterpret_cast<float*>(ds + S2_ATT);
    if (tid < 80) att_s[tid] = __ldg(att + tid);

    const float4* A4 = reinterpret_cast<const float4*>(A);
    for (int idx = tid; idx < 128 * 16; idx += 256) {
        int r = idx >> 4, c4 = idx & 15;
        float4 v = make_float4(0.f, 0.f, 0.f, 0.f);
        int gn = row0 + r;
        if (gn < NN) v = A4[gn * 16 + c4];
        uint2 hi, lo;
        cvt_split2(v.x, v.y, hi.x, lo.x);
        cvt_split2(v.z, v.w, hi.y, lo.y);
        int off = r * S2AS + c4 * 8;
        *reinterpret_cast<uint2*>(ds + S2_AHI + off) = hi;
        *reinterpret_cast<uint2*>(ds + S2_ALO + off) = lo;
    }
    for (int idx = tid; idx < 40 * S2AS / 16; idx += 256) {
        reinterpret_cast<uint4*>(ds + S2_BHI)[idx] =
            reinterpret_cast<const uint4*>(g_w1h)[idx];
        reinterpret_cast<uint4*>(ds + S2_BLO)[idx] =
            reinterpret_cast<const uint4*>(g_w1l)[idx];
    }
    __syncthreads();

    int wid = tid >> 5;
    int lane = tid & 31;
    int g = lane >> 2;
    int t = lane & 3;

    float c[5][4];
#pragma unroll
    for (int nt = 0; nt < 5; ++nt)
#pragma unroll
        for (int q = 0; q < 4; ++q) c[nt][q] = 0.f;

    int arow = (wid * 16 + g) * S2AS + t * 4;
    int brow = g * S2AS + t * 4;

#pragma unroll
    for (int kk = 0; kk < 4; ++kk) {
        int kb = kk * 32;
        uint32_t aH[4], aL[4], bH[5][2], bL[5][2];
        int base = arow + kb;
        aH[0] = *reinterpret_cast<const uint32_t*>(ds + S2_AHI + base);
        aH[1] = *reinterpret_cast<const uint32_t*>(ds + S2_AHI + base + 8 * S2AS);
        aH[2] = *reinterpret_cast<const uint32_t*>(ds + S2_AHI + base + 16);
        aH[3] = *reinterpret_cast<const uint32_t*>(ds + S2_AHI + base + 8 * S2AS + 16);
        aL[0] = *reinterpret_cast<const uint32_t*>(ds + S2_ALO + base);
        aL[1] = *reinterpret_cast<const uint32_t*>(ds + S2_ALO + base + 8 * S2AS);
        aL[2] = *reinterpret_cast<const uint32_t*>(ds + S2_ALO + base + 16);
        aL[3] = *reinterpret_cast<const uint32_t*>(ds + S2_ALO + base + 8 * S2AS + 16);
#pragma unroll
        for (int nt = 0; nt < 5; ++nt) {
            int bb = brow + nt * 8 * S2AS + kb;
            bH[nt][0] = *reinterpret_cast<const uint32_t*>(ds + S2_BHI + bb);
            bH[nt][1] = *reinterpret_cast<const uint32_t*>(ds + S2_BHI + bb + 16);
            bL[nt][0] = *reinterpret_cast<const uint32_t*>(ds + S2_BLO + bb);
            bL[nt][1] = *reinterpret_cast<const uint32_t*>(ds + S2_BLO + bb + 16);
        }
#pragma unroll
        for (int nt = 0; nt < 5; ++nt) {
            mma16816(c[nt], aH, bH[nt]);
            mma16816(c[nt], aH, bL[nt]);
            mma16816(c[nt], aL, bH[nt]);
        }
    }

    int lr0 = wid * 16 + g, lr1 = lr0 + 8;
    int gn0 = row0 + lr0, gn1 = row0 + lr1;
    float pd0 = 0.f, ps0 = 0.f, pd1 = 0.f, ps1 = 0.f;
#pragma unroll
    for (int nt = 0; nt < 5; ++nt) {
        int col = nt * 8 + 2 * t;
        float c0 = c[nt][0], c1 = c[nt][1], c2 = c[nt][2], c3 = c[nt][3];
        pd0 += c0 * att_s[col] + c1 * att_s[col + 1];
        ps0 += c0 * att_s[40 + col] + c1 * att_s[40 + col + 1];
        pd1 += c2 * att_s[col] + c3 * att_s[col + 1];
        ps1 += c2 * att_s[40 + col] + c3 * att_s[40 + col + 1];
        if (gn0 < NN)
            *reinterpret_cast<float2*>(C + (size_t)gn0 * 40 + col) = make_float2(c0, c1);
        if (gn1 < NN)
            *reinterpret_cast<float2*>(C + (size_t)gn1 * 40 + col) = make_float2(c2, c3);
    }
#pragma unroll
    for (int o = 1; o <= 2; o <<= 1) {
        pd0 += __shfl_down_sync(0xffffffffu, pd0, o);
        ps0 += __shfl_down_sync(0xffffffffu, ps0, o);
        pd1 += __shfl_down_sync(0xffffffffu, pd1, o);
        ps1 += __shfl_down_sync(0xffffffffu, ps1, o);
    }
    if (t == 0) {
        if (gn0 < NN) {
            adst[gn0] = pd0;
            asrc[gn0] = ps0;
            wself[gn0] = __expf(lrelu(pd0 + ps0));
        }
        if (gn1 < NN) {
            adst[gn1] = pd1;
            asrc[gn1] = ps1;
            wself[gn1] = __expf(lrelu(pd1 + ps1));
        }
    }
}

// ---------------- CSR build: fused scan with decoupled lookback ----------------
#define SCAN_FLAG 0x40000000

__global__ void __launch_bounds__(1024) scan_fused_kernel(
    const int* __restrict__ deg, int* __restrict__ rowp, int* __restrict__ cursor,
    int* __restrict__ partial) {
    __shared__ int wsum[32];
    __shared__ int s_off;
    int tid = threadIdx.x, b = blockIdx.x;
    int lane = tid & 31, w = tid >> 5;
    int i = b * 1024 + tid;
    int v = (i < NN) ? deg[i] : 0;

    int x = v;
#pragma unroll
    for (int o = 1; o < 32; o <<= 1) {
        int y = __shfl_up_sync(0xffffffffu, x, o);
        if (lane >= o) x += y;
    }
    if (lane == 31) wsum[w] = x;
    __syncthreads();
    if (w == 0) {
        int s = wsum[lane];
#pragma unroll
        for (int o = 1; o < 32; o <<= 1) {
            int y = __shfl_up_sync(0xffffffffu, s, o);
            if (lane >= o) s += y;
        }
        wsum[lane] = s;
        if (lane == 31) {
            atomicExch(partial + b, s | SCAN_FLAG);
        }
        int acc = 0;
        for (int j = lane; j < b; j += 32) {
            int p;
            do {
                p = *((volatile int*)(partial + j));
            } while (!(p & SCAN_FLAG));
            acc += p & (SCAN_FLAG - 1);
        }
#pragma unroll
        for (int o = 16; o; o >>= 1) acc += __shfl_xor_sync(0xffffffffu, acc, o);
        if (lane == 0) s_off = acc;
    }
    __syncthreads();
    int excl = ((w == 0) ? 0 : wsum[w - 1]) + x - v + s_off;
    if (i < NN) {
        rowp[i] = excl;
        cursor[i] = excl;
    }
    if (i == 0) rowp[NN] = EE;
}

// ---------------- scatter: 4 edges/thread, independent atomic chains ----------------
__global__ void __launch_bounds__(256) scatter_kernel(
    const int* __restrict__ ei, int* __restrict__ cursor, int* __restrict__ col) {
    int t = blockIdx.x * 256 + threadIdx.x;
    if (t < EE / 4) {
        int4 s4 = reinterpret_cast<const int4*>(ei)[t];
        int4 d4 = reinterpret_cast<const int4*>(ei + EE)[t];
        // batch all atomics (distinct return regs) before the dependent stores
        int p0 = atomicAdd(cursor + d4.x, 1);
        int p1 = atomicAdd(cursor + d4.y, 1);
        int p2 = atomicAdd(cursor + d4.z, 1);
        int p3 = atomicAdd(cursor + d4.w, 1);
        col[p0] = s4.x;
        col[p1] = s4.y;
        col[p2] = s4.z;
        col[p3] = s4.w;
    }
}

// ---------------- aggregation: shfl-free gather, inline edge weights ----------------
// czero (nullable): buffer to zero for the next replay (cursor, consumed by scatter).
template <int CH, bool RELU, bool LSM>
__global__ void aggregate_kernel(const float* __restrict__ h, const float* __restrict__ adst,
                                 const float* __restrict__ asrc,
                                 const float* __restrict__ wself,
                                 const int* __restrict__ rowp, const int* __restrict__ col,
                                 float* __restrict__ out, int* __restrict__ czero) {
    constexpr int NL = CH / 4;    // 16 or 10
    constexpr int NG = 32 / NL;   // 2 or 3

    int gtid = blockIdx.x * blockDim.x + threadIdx.x;
    if (czero != nullptr && gtid < NN) czero[gtid] = 0;

    int d = gtid >> 5;
    int lane = threadIdx.x & 31;
    if (d >= NN) return;

    int rs = __ldg(rowp + d), re = __ldg(rowp + d + 1);
    float ad = __ldg(adst + d);

    int group = lane / NL;
    if (group >= NG) group = NG - 1;
    int cid = lane - group * NL;
    if (cid >= NL) cid -= NL;

    const float4* __restrict__ h4 = reinterpret_cast<const float4*>(h);

    float4 acc = make_float4(0.f, 0.f, 0.f, 0.f);
    float psum = 0.f;

    for (int j = rs + group; j < re; j += NG) {
        int s = __ldg(col + j);
        float e = __expf(lrelu(ad + __ldg(asrc + s)));
        float4 hv = __ldg(h4 + s * NL + cid);
        psum += e;
        acc.x += e * hv.x;
        acc.y += e * hv.y;
        acc.z += e * hv.z;
        acc.w += e * hv.w;
    }

    float es = __ldg(wself + d);

    if (group == 0 && lane < NL) {
        float4 hv = __ldg(h4 + d * NL + cid);
        acc.x += es * hv.x;
        acc.y += es * hv.y;
        acc.z += es * hv.z;
        acc.w += es * hv.w;
    }

#pragma unroll
    for (int g = 1; g < NG; ++g) {
        int sl = lane + g * NL;
        float px = __shfl_sync(0xffffffffu, acc.x, sl & 31);
        float py = __shfl_sync(0xffffffffu, acc.y, sl & 31);
        float pz = __shfl_sync(0xffffffffu, acc.z, sl & 31);
        float pw = __shfl_sync(0xffffffffu, acc.w, sl & 31);
        float pp = __shfl_sync(0xffffffffu, psum, g * NL);
        if (lane < NL) {
            acc.x += px;
            acc.y += py;
            acc.z += pz;
            acc.w += pw;
        }
        psum = (lane == 0) ? psum + pp : psum;
    }
    psum = __shfl_sync(0xffffffffu, psum, 0) + es;

    float4 v = make_float4(0.f, 0.f, 0.f, 0.f);
    if (lane < NL) {
        float inv = 1.0f / psum;
        v.x = acc.x * inv;
        v.y = acc.y * inv;
        v.z = acc.z * inv;
        v.w = acc.w * inv;
    }

    if (LSM) {
        float vm = -1e30f;
        if (lane < NL) vm = fmaxf(fmaxf(v.x, v.y), fmaxf(v.z, v.w));
#pragma unroll
        for (int o = 16; o; o >>= 1) vm = fmaxf(vm, __shfl_xor_sync(0xffffffffu, vm, o));
        float se = 0.f;
        if (lane < NL)
            se = __expf(v.x - vm) + __expf(v.y - vm) + __expf(v.z - vm) + __expf(v.w - vm);
#pragma unroll
        for (int o = 16; o; o >>= 1) se += __shfl_xor_sync(0xffffffffu, se, o);
        float l = vm + logf(se);
        if (lane < NL) {
            v.x -= l;
            v.y -= l;
            v.z -= l;
            v.w -= l;
            reinterpret_cast<float4*>(out)[(size_t)d * NL + cid] = v;
        }
    } else {
        if (lane < NL) {
            if (RELU) {
                v.x = fmaxf(v.x, 0.f);
                v.y = fmaxf(v.y, 0.f);
                v.z = fmaxf(v.z, 0.f);
                v.w = fmaxf(v.w, 0.f);
            }
            reinterpret_cast<float4*>(out)[(size_t)d * NL + cid] = v;
        }
    }
}

// ---------------- launch ----------------
extern "C" void kernel_launch(void* const* d_in, const int* in_sizes, int n_in,
                              void* d_out, int out_size) {
    (void)in_sizes;
    (void)n_in;
    (void)out_size;
    const float* x    = (const float*)d_in[0];
    const int*   ei   = (const int*)d_in[1];
    const float* W0   = (const float*)d_in[2];
    const float* att0 = (const float*)d_in[3];
    const float* W1   = (const float*)d_in[4];
    const float* att1 = (const float*)d_in[5];
    float* out = (float*)d_out;

    void *p;
    float *h0, *h1, *h2, *adst, *asrc, *wself;
    int *rowptr, *cursor, *colp, *bsum;
    cudaGetSymbolAddress(&p, g_h0);     h0 = (float*)p;
    cudaGetSymbolAddress(&p, g_h1);     h1 = (float*)p;
    cudaGetSymbolAddress(&p, g_h2);     h2 = (float*)p;
    cudaGetSymbolAddress(&p, g_adst);   adst = (float*)p;
    cudaGetSymbolAddress(&p, g_asrc);   asrc = (float*)p;
    cudaGetSymbolAddress(&p, g_wself);  wself = (float*)p;
    cudaGetSymbolAddress(&p, g_rowptr); rowptr = (int*)p;
    cudaGetSymbolAddress(&p, g_cursor); cursor = (int*)p;
    cudaGetSymbolAddress(&p, g_col);    colp = (int*)p;
    cudaGetSymbolAddress(&p, g_bsum);   bsum = (int*)p;

    cudaFuncSetAttribute(gemm1_mma_kernel,
                         cudaFuncAttributeMaxDynamicSharedMemorySize, SM_TOT);
    cudaFuncSetAttribute(gemm2_mma_kernel,
                         cudaFuncAttributeMaxDynamicSharedMemorySize, S2_TOT);

    const int TB = 256;
    int warp_blocks = (NN * 32 + TB - 1) / TB; // 12500

    // prep: convert W0/W1 once into pre-swizzled hi/lo buffers; reset bsum
    prep_w_kernel<<<11, TB>>>(W0, W1, bsum);

    // Layer-1 GEMM (M=64 tiles, 3 CTAs/SM) + degree histogram
    gemm1_mma_kernel<<<GB1, TB, SM_TOT>>>(x, att0, h0, adst, asrc, wself, ei, cursor);

    // CSR finalize: one-kernel scan + scatter (4 edges/thread)
    scan_fused_kernel<<<NBLK, 1024>>>(cursor, rowptr, cursor, bsum);
    scatter_kernel<<<(EE / 4 + TB - 1) / TB, TB>>>(ei, cursor, colp);

    // Layer 1 aggregation: 64ch, relu; also re-zeroes cursor for the next replay
    aggregate_kernel<64, true, false><<<warp_blocks, TB>>>(h0, adst, asrc, wself, rowptr,
                                                           colp, h1, cursor);

    // Layer 2: 64 -> 40 (warp mma.sync), then fused log_softmax aggregation
    gemm2_mma_kernel<<<GB2, TB, S2_TOT>>>(h1, att1, h2, adst, asrc, wself);
    aggregate_kernel<40, false, true><<<warp_blocks, TB>>>(h2, adst, asrc, wself, rowptr,
                                                           colp, out, nullptr);
}

// round 17
// speedup vs baseline: 1.0686x; 1.0252x over previous
#include <cuda_runtime.h>
#include <cuda_bf16.h>
#include <cstdint>

#define NN 100000
#define EE 1600000
#define NBLK 98          // scan blocks: ceil(NN/1024)
#define SCB 391          // scatter blocks: ceil(EE/4/1024)
#define GB1 1563         // gemm1 blocks: ceil(NN/64)
#define GB2 782          // gemm2 blocks: ceil(NN/128)

#define SAS 272          // gemm1 smem row stride (bytes)
#define S2AS 144         // gemm2 smem row stride (bytes)

// ---------------- scratch ----------------
__device__ __align__(16) float g_h0[NN * 64];
__device__ __align__(16) float g_h1[NN * 64];
__device__ __align__(16) float g_h2[NN * 40];
__device__ float g_adst[NN];
__device__ float g_asrc[NN];
__device__ float g_wself[NN];
__device__ int   g_rowptr[NN + 1];
__device__ int   g_cursor[NN];   // zero at load; re-zeroed by agg1 tail each call
__device__ int   g_col[EE];
__device__ int   g_bsum[128];    // re-zeroed by prep each call
__device__ int   g_done;         // scan-complete counter; re-zeroed by prep
// pre-swizzled W tiles (hi/lo bf16, exact smem layout incl. padding)
__device__ __align__(16) char g_w0h[64 * SAS];
__device__ __align__(16) char g_w0l[64 * SAS];
__device__ __align__(16) char g_w1h[40 * S2AS];
__device__ __align__(16) char g_w1l[40 * S2AS];

__device__ __forceinline__ float lrelu(float x) { return x < 0.f ? 0.2f * x : x; }

// ---------------- warp mma helper (sm_80+ baseline PTX; HMMA on Blackwell) ----------
__device__ __forceinline__ void mma16816(float* c, const uint32_t* a, const uint32_t* b) {
    asm volatile(
        "mma.sync.aligned.m16n8k16.row.col.f32.bf16.bf16.f32 "
        "{%0,%1,%2,%3}, {%4,%5,%6,%7}, {%8,%9}, {%0,%1,%2,%3};"
        : "+f"(c[0]), "+f"(c[1]), "+f"(c[2]), "+f"(c[3])
        : "r"(a[0]), "r"(a[1]), "r"(a[2]), "r"(a[3]), "r"(b[0]), "r"(b[1]));
}

// paired split-convert: hi = {bf16(y), bf16(x)}, lo = {bf16(y-hi.y), bf16(x-hi.x)}
__device__ __forceinline__ void cvt_split2(float x, float y, uint32_t& hi, uint32_t& lo) {
    asm("cvt.rn.bf16x2.f32 %0, %1, %2;" : "=r"(hi) : "f"(y), "f"(x));
    float lx = x - __uint_as_float(hi << 16);
    float ly = y - __uint_as_float(hi & 0xFFFF0000u);
    asm("cvt.rn.bf16x2.f32 %0, %1, %2;" : "=r"(lo) : "f"(ly), "f"(lx));
}

// ---------------- prep: convert W0/W1 once into pre-swizzled hi/lo buffers ----------
__global__ void __launch_bounds__(256) prep_w_kernel(const float* __restrict__ W0,
                                                     const float* __restrict__ W1,
                                                     int* __restrict__ bsum,
                                                     int* __restrict__ done) {
    int tid = blockIdx.x * 256 + threadIdx.x;
    if (tid < 128) bsum[tid] = 0;
    if (tid == 128) *done = 0;
    if (tid < 64 * 32) {
        int r = tid >> 5, c4 = tid & 31;
        float4 v = reinterpret_cast<const float4*>(W0)[r * 32 + c4];
        uint2 hi, lo;
        cvt_split2(v.x, v.y, hi.x, lo.x);
        cvt_split2(v.z, v.w, hi.y, lo.y);
        int off = r * SAS + c4 * 8;
        *reinterpret_cast<uint2*>(g_w0h + off) = hi;
        *reinterpret_cast<uint2*>(g_w0l + off) = lo;
    }
    int t1 = tid - 64 * 32;
    if (t1 >= 0 && t1 < 40 * 16) {
        int r = t1 >> 4, c4 = t1 & 15;
        float4 v = reinterpret_cast<const float4*>(W1)[r * 16 + c4];
        uint2 hi, lo;
        cvt_split2(v.x, v.y, hi.x, lo.x);
        cvt_split2(v.z, v.w, hi.y, lo.y);
        int off = r * S2AS + c4 * 8;
        *reinterpret_cast<uint2*>(g_w1h + off) = hi;
        *reinterpret_cast<uint2*>(g_w1l + off) = lo;
    }
}

// ---------------- layer-1 GEMM: M=64 tiles, 3 CTAs/SM, bf16 2-term split ------------
// Embedded histogram (fire-and-forget RED, no return) overlaps the prologue.
#define SM_ATT 0
#define SM_PD  512
#define SM_PS  768
#define SM_AHI 1024
#define SM_ALO (SM_AHI + 64 * SAS)
#define SM_BHI (SM_ALO + 64 * SAS)
#define SM_BLO (SM_BHI + 64 * SAS)
#define SM_TOT (SM_BLO + 64 * SAS)

__global__ void __launch_bounds__(256) gemm1_mma_kernel(
    const float* __restrict__ A, const float* __restrict__ att, float* __restrict__ C,
    float* __restrict__ adst, float* __restrict__ asrc, float* __restrict__ wself,
    const int* __restrict__ ei, int* __restrict__ deg) {
    extern __shared__ char ds[];
    int tid = threadIdx.x;
    int row0 = blockIdx.x * 64;

    // embedded degree histogram: 1024 edges per CTA (fire-and-forget RED)
    {
        int t4 = blockIdx.x * 256 + tid;
        if (t4 < EE / 4) {
            int4 d4 = reinterpret_cast<const int4*>(ei + EE)[t4];
            atomicAdd(deg + d4.x, 1);
            atomicAdd(deg + d4.y, 1);
            atomicAdd(deg + d4.z, 1);
            atomicAdd(deg + d4.w, 1);
        }
    }

    float* att_s = reinterpret_cast<float*>(ds + SM_ATT);
    float* spd = reinterpret_cast<float*>(ds + SM_PD);
    float* sps = reinterpret_cast<float*>(ds + SM_PS);
    if (tid < 128) att_s[tid] = __ldg(att + tid);
    if (tid < 64) {
        spd[tid] = 0.f;
        sps[tid] = 0.f;
    }

    // A tile: 64x128 fp32 -> bf16 hi/lo via paired cvt
    const float4* A4 = reinterpret_cast<const float4*>(A);
    for (int idx = tid; idx < 64 * 32; idx += 256) {
        int r = idx >> 5, c4 = idx & 31;
        float4 v = make_float4(0.f, 0.f, 0.f, 0.f);
        int gn = row0 + r;
        if (gn < NN) v = A4[gn * 32 + c4];
        uint2 hi, lo;
        cvt_split2(v.x, v.y, hi.x, lo.x);
        cvt_split2(v.z, v.w, hi.y, lo.y);
        int off = r * SAS + c4 * 8;
        *reinterpret_cast<uint2*>(ds + SM_AHI + off) = hi;
        *reinterpret_cast<uint2*>(ds + SM_ALO + off) = lo;
    }
    // B tile: plain uint4 copy of pre-swizzled W0 (L2-resident)
    for (int idx = tid; idx < 64 * SAS / 16; idx += 256) {
        reinterpret_cast<uint4*>(ds + SM_BHI)[idx] =
            reinterpret_cast<const uint4*>(g_w0h)[idx];
        reinterpret_cast<uint4*>(ds + SM_BLO)[idx] =
            reinterpret_cast<const uint4*>(g_w0l)[idx];
    }
    __syncthreads();

    int wid = tid >> 5;
    int lane = tid & 31;
    int wm = wid & 3;
    int wn = wid >> 2;
    int g = lane >> 2;
    int t = lane & 3;

    float c[4][4];
#pragma unroll
    for (int nt = 0; nt < 4; ++nt)
#pragma unroll
        for (int q = 0; q < 4; ++q) c[nt][q] = 0.f;

    int arow = (wm * 16 + g) * SAS + t * 4;
    int brow = (wn * 32 + g) * SAS + t * 4;

#pragma unroll
    for (int kk = 0; kk < 8; ++kk) {
        int kb = kk * 32;
        uint32_t aH[4], aL[4], bH[4][2], bL[4][2];
        int base = arow + kb;
        aH[0] = *reinterpret_cast<const uint32_t*>(ds + SM_AHI + base);
        aH[1] = *reinterpret_cast<const uint32_t*>(ds + SM_AHI + base + 8 * SAS);
        aH[2] = *reinterpret_cast<const uint32_t*>(ds + SM_AHI + base + 16);
        aH[3] = *reinterpret_cast<const uint32_t*>(ds + SM_AHI + base + 8 * SAS + 16);
        aL[0] = *reinterpret_cast<const uint32_t*>(ds + SM_ALO + base);
        aL[1] = *reinterpret_cast<const uint32_t*>(ds + SM_ALO + base + 8 * SAS);
        aL[2] = *reinterpret_cast<const uint32_t*>(ds + SM_ALO + base + 16);
        aL[3] = *reinterpret_cast<const uint32_t*>(ds + SM_ALO + base + 8 * SAS + 16);
#pragma unroll
        for (int nt = 0; nt < 4; ++nt) {
            int bb = brow + nt * 8 * SAS + kb;
            bH[nt][0] = *reinterpret_cast<const uint32_t*>(ds + SM_BHI + bb);
            bH[nt][1] = *reinterpret_cast<const uint32_t*>(ds + SM_BHI + bb + 16);
            bL[nt][0] = *reinterpret_cast<const uint32_t*>(ds + SM_BLO + bb);
            bL[nt][1] = *reinterpret_cast<const uint32_t*>(ds + SM_BLO + bb + 16);
        }
#pragma unroll
        for (int nt = 0; nt < 4; ++nt) {
            mma16816(c[nt], aH, bH[nt]);
            mma16816(c[nt], aH, bL[nt]);
            mma16816(c[nt], aL, bH[nt]);
        }
    }

    // epilogue: store C + alpha dot partials (quad reduce -> smem atomics)
    int lr0 = wm * 16 + g, lr1 = lr0 + 8;
    int gn0 = row0 + lr0, gn1 = row0 + lr1;
    float pd0 = 0.f, ps0 = 0.f, pd1 = 0.f, ps1 = 0.f;
#pragma unroll
    for (int nt = 0; nt < 4; ++nt) {
        int col = wn * 32 + nt * 8 + 2 * t;
        float c0 = c[nt][0], c1 = c[nt][1], c2 = c[nt][2], c3 = c[nt][3];
        pd0 += c0 * att_s[col] + c1 * att_s[col + 1];
        ps0 += c0 * att_s[64 + col] + c1 * att_s[64 + col + 1];
        pd1 += c2 * att_s[col] + c3 * att_s[col + 1];
        ps1 += c2 * att_s[64 + col] + c3 * att_s[64 + col + 1];
        if (gn0 < NN)
            *reinterpret_cast<float2*>(C + (size_t)gn0 * 64 + col) = make_float2(c0, c1);
        if (gn1 < NN)
            *reinterpret_cast<float2*>(C + (size_t)gn1 * 64 + col) = make_float2(c2, c3);
    }
#pragma unroll
    for (int o = 1; o <= 2; o <<= 1) {
        pd0 += __shfl_down_sync(0xffffffffu, pd0, o);
        ps0 += __shfl_down_sync(0xffffffffu, ps0, o);
        pd1 += __shfl_down_sync(0xffffffffu, pd1, o);
        ps1 += __shfl_down_sync(0xffffffffu, ps1, o);
    }
    if (t == 0) {
        atomicAdd(spd + lr0, pd0);
        atomicAdd(sps + lr0, ps0);
        atomicAdd(spd + lr1, pd1);
        atomicAdd(sps + lr1, ps1);
    }
    __syncthreads();
    if (tid < 64) {
        int gn = row0 + tid;
        if (gn < NN) {
            float pd = spd[tid], ps = sps[tid];
            adst[gn] = pd;
            asrc[gn] = ps;
            wself[gn] = __expf(lrelu(pd + ps));
        }
    }
}

// ---------------- layer-2 GEMM (warp mma, bf16 2-term split, M=128 N=40 K=64) --------
#define S2_ATT 0
#define S2_AHI 512
#define S2_ALO (S2_AHI + 128 * S2AS)
#define S2_BHI (S2_ALO + 128 * S2AS)
#define S2_BLO (S2_BHI + 40 * S2AS)
#define S2_TOT (S2_BLO + 40 * S2AS)

__global__ void __launch_bounds__(256) gemm2_mma_kernel(
    const float* __restrict__ A, const float* __restrict__ att, float* __restrict__ C,
    float* __restrict__ adst, float* __restrict__ asrc, float* __restrict__ wself) {
    extern __shared__ char ds[];
    int tid = threadIdx.x;
    int row0 = blockIdx.x * 128;

    float* att_s = reinterpret_cast<float*>(ds + S2_ATT);
    if (tid < 80) att_s[tid] = __ldg(att + tid);

    const float4* A4 = reinterpret_cast<const float4*>(A);
    for (int idx = tid; idx < 128 * 16; idx += 256) {
        int r = idx >> 4, c4 = idx & 15;
        float4 v = make_float4(0.f, 0.f, 0.f, 0.f);
        int gn = row0 + r;
        if (gn < NN) v = A4[gn * 16 + c4];
        uint2 hi, lo;
        cvt_split2(v.x, v.y, hi.x, lo.x);
        cvt_split2(v.z, v.w, hi.y, lo.y);
        int off = r * S2AS + c4 * 8;
        *reinterpret_cast<uint2*>(ds + S2_AHI + off) = hi;
        *reinterpret_cast<uint2*>(ds + S2_ALO + off) = lo;
    }
    for (int idx = tid; idx < 40 * S2AS / 16; idx += 256) {
        reinterpret_cast<uint4*>(ds + S2_BHI)[idx] =
            reinterpret_cast<const uint4*>(g_w1h)[idx];
        reinterpret_cast<uint4*>(ds + S2_BLO)[idx] =
            reinterpret_cast<const uint4*>(g_w1l)[idx];
    }
    __syncthreads();

    int wid = tid >> 5;
    int lane = tid & 31;
    int g = lane >> 2;
    int t = lane & 3;

    float c[5][4];
#pragma unroll
    for (int nt = 0; nt < 5; ++nt)
#pragma unroll
        for (int q = 0; q < 4; ++q) c[nt][q] = 0.f;

    int arow = (wid * 16 + g) * S2AS + t * 4;
    int brow = g * S2AS + t * 4;

#pragma unroll
    for (int kk = 0; kk < 4; ++kk) {
        int kb = kk * 32;
        uint32_t aH[4], aL[4], bH[5][2], bL[5][2];
        int base = arow + kb;
        aH[0] = *reinterpret_cast<const uint32_t*>(ds + S2_AHI + base);
        aH[1] = *reinterpret_cast<const uint32_t*>(ds + S2_AHI + base + 8 * S2AS);
        aH[2] = *reinterpret_cast<const uint32_t*>(ds + S2_AHI + base + 16);
        aH[3] = *reinterpret_cast<const uint32_t*>(ds + S2_AHI + base + 8 * S2AS + 16);
        aL[0] = *reinterpret_cast<const uint32_t*>(ds + S2_ALO + base);
        aL[1] = *reinterpret_cast<const uint32_t*>(ds + S2_ALO + base + 8 * S2AS);
        aL[2] = *reinterpret_cast<const uint32_t*>(ds + S2_ALO + base + 16);
        aL[3] = *reinterpret_cast<const uint32_t*>(ds + S2_ALO + base + 8 * S2AS + 16);
#pragma unroll
        for (int nt = 0; nt < 5; ++nt) {
            int bb = brow + nt * 8 * S2AS + kb;
            bH[nt][0] = *reinterpret_cast<const uint32_t*>(ds + S2_BHI + bb);
            bH[nt][1] = *reinterpret_cast<const uint32_t*>(ds + S2_BHI + bb + 16);
            bL[nt][0] = *reinterpret_cast<const uint32_t*>(ds + S2_BLO + bb);
            bL[nt][1] = *reinterpret_cast<const uint32_t*>(ds + S2_BLO + bb + 16);
        }
#pragma unroll
        for (int nt = 0; nt < 5; ++nt) {
            mma16816(c[nt], aH, bH[nt]);
            mma16816(c[nt], aH, bL[nt]);
            mma16816(c[nt], aL, bH[nt]);
        }
    }

    int lr0 = wid * 16 + g, lr1 = lr0 + 8;
    int gn0 = row0 + lr0, gn1 = row0 + lr1;
    float pd0 = 0.f, ps0 = 0.f, pd1 = 0.f, ps1 = 0.f;
#pragma unroll
    for (int nt = 0; nt < 5; ++nt) {
        int col = nt * 8 + 2 * t;
        float c0 = c[nt][0], c1 = c[nt][1], c2 = c[nt][2], c3 = c[nt][3];
        pd0 += c0 * att_s[col] + c1 * att_s[col + 1];
        ps0 += c0 * att_s[40 + col] + c1 * att_s[40 + col + 1];
        pd1 += c2 * att_s[col] + c3 * att_s[col + 1];
        ps1 += c2 * att_s[40 + col] + c3 * att_s[40 + col + 1];
        if (gn0 < NN)
            *reinterpret_cast<float2*>(C + (size_t)gn0 * 40 + col) = make_float2(c0, c1);
        if (gn1 < NN)
            *reinterpret_cast<float2*>(C + (size_t)gn1 * 40 + col) = make_float2(c2, c3);
    }
#pragma unroll
    for (int o = 1; o <= 2; o <<= 1) {
        pd0 += __shfl_down_sync(0xffffffffu, pd0, o);
        ps0 += __shfl_down_sync(0xffffffffu, ps0, o);
        pd1 += __shfl_down_sync(0xffffffffu, pd1, o);
        ps1 += __shfl_down_sync(0xffffffffu, ps1, o);
    }
    if (t == 0) {
        if (gn0 < NN) {
            adst[gn0] = pd0;
            asrc[gn0] = ps0;
            wself[gn0] = __expf(lrelu(pd0 + ps0));
        }
        if (gn1 < NN) {
            adst[gn1] = pd1;
            asrc[gn1] = ps1;
            wself[gn1] = __expf(lrelu(pd1 + ps1));
        }
    }
}

// ---------------- fused CSR: scan (blocks < NBLK) + gated scatter (rest) ------------
// Scan blocks run the decoupled-lookback scan, fence, then bump `done`.
// Scatter blocks spin until done == NBLK, then run the 4-edge/thread scatter.
// Deadlock-free: 1024-thr CTAs -> 2/SM -> wave 1 holds 296 blocks >= 98 scan blocks.
#define SCAN_FLAG 0x40000000

__global__ void __launch_bounds__(1024) scan_scatter_kernel(
    const int* __restrict__ deg, int* __restrict__ rowp, int* __restrict__ cursor,
    int* __restrict__ partial, const int* __restrict__ ei, int* __restrict__ col,
    int* __restrict__ done) {
    int tid = threadIdx.x, b = blockIdx.x;

    if (b < NBLK) {
        __shared__ int wsum[32];
        __shared__ int s_off;
        int lane = tid & 31, w = tid >> 5;
        int i = b * 1024 + tid;
        int v = (i < NN) ? deg[i] : 0;

        int x = v;
#pragma unroll
        for (int o = 1; o < 32; o <<= 1) {
            int y = __shfl_up_sync(0xffffffffu, x, o);
            if (lane >= o) x += y;
        }
        if (lane == 31) wsum[w] = x;
        __syncthreads();
        if (w == 0) {
            int s = wsum[lane];
#pragma unroll
            for (int o = 1; o < 32; o <<= 1) {
                int y = __shfl_up_sync(0xffffffffu, s, o);
                if (lane >= o) s += y;
            }
            wsum[lane] = s;
            if (lane == 31) {
                atomicExch(partial + b, s | SCAN_FLAG);
            }
            int acc = 0;
            for (int j = lane; j < b; j += 32) {
                int p;
                do {
                    p = *((volatile int*)(partial + j));
                } while (!(p & SCAN_FLAG));
                acc += p & (SCAN_FLAG - 1);
            }
#pragma unroll
            for (int o = 16; o; o >>= 1) acc += __shfl_xor_sync(0xffffffffu, acc, o);
            if (lane == 0) s_off = acc;
        }
        __syncthreads();
        int excl = ((w == 0) ? 0 : wsum[w - 1]) + x - v + s_off;
        if (i < NN) {
            rowp[i] = excl;
            cursor[i] = excl;
        }
        if (i == 0) rowp[NN] = EE;
        // release: make rowp/cursor visible, then signal completion
        __syncthreads();
        if (tid == 0) {
            __threadfence();
            atomicAdd(done, 1);
        }
    } else {
        // gate: wait for all scan blocks
        if (tid == 0) {
            while (*((volatile int*)done) < NBLK) {
            }
        }
        __syncthreads();
        int t = (b - NBLK) * 1024 + tid;
        if (t < EE / 4) {
            int4 s4 = reinterpret_cast<const int4*>(ei)[t];
            int4 d4 = reinterpret_cast<const int4*>(ei + EE)[t];
            int p0 = atomicAdd(cursor + d4.x, 1);
            int p1 = atomicAdd(cursor + d4.y, 1);
            int p2 = atomicAdd(cursor + d4.z, 1);
            int p3 = atomicAdd(cursor + d4.w, 1);
            col[p0] = s4.x;
            col[p1] = s4.y;
            col[p2] = s4.z;
            col[p3] = s4.w;
        }
    }
}

// ---------------- aggregation: shfl-free gather, inline edge weights ----------------
// czero (nullable): buffer to zero for the next replay (cursor, consumed by scatter).
template <int CH, bool RELU, bool LSM>
__global__ void aggregate_kernel(const float* __restrict__ h, const float* __restrict__ adst,
                                 const float* __restrict__ asrc,
                                 const float* __restrict__ wself,
                                 const int* __restrict__ rowp, const int* __restrict__ col,
                                 float* __restrict__ out, int* __restrict__ czero) {
    constexpr int NL = CH / 4;    // 16 or 10
    constexpr int NG = 32 / NL;   // 2 or 3

    int gtid = blockIdx.x * blockDim.x + threadIdx.x;
    if (czero != nullptr && gtid < NN) czero[gtid] = 0;

    int d = gtid >> 5;
    int lane = threadIdx.x & 31;
    if (d >= NN) return;

    int rs = __ldg(rowp + d), re = __ldg(rowp + d + 1);
    float ad = __ldg(adst + d);

    int group = lane / NL;
    if (group >= NG) group = NG - 1;
    int cid = lane - group * NL;
    if (cid >= NL) cid -= NL;

    const float4* __restrict__ h4 = reinterpret_cast<const float4*>(h);

    float4 acc = make_float4(0.f, 0.f, 0.f, 0.f);
    float psum = 0.f;

    for (int j = rs + group; j < re; j += NG) {
        int s = __ldg(col + j);
        float e = __expf(lrelu(ad + __ldg(asrc + s)));
        float4 hv = __ldg(h4 + s * NL + cid);
        psum += e;
        acc.x += e * hv.x;
        acc.y += e * hv.y;
        acc.z += e * hv.z;
        acc.w += e * hv.w;
    }

    float es = __ldg(wself + d);

    if (group == 0 && lane < NL) {
        float4 hv = __ldg(h4 + d * NL + cid);
        acc.x += es * hv.x;
        acc.y += es * hv.y;
        acc.z += es * hv.z;
        acc.w += es * hv.w;
    }

#pragma unroll
    for (int g = 1; g < NG; ++g) {
        int sl = lane + g * NL;
        float px = __shfl_sync(0xffffffffu, acc.x, sl & 31);
        float py = __shfl_sync(0xffffffffu, acc.y, sl & 31);
        float pz = __shfl_sync(0xffffffffu, acc.z, sl & 31);
        float pw = __shfl_sync(0xffffffffu, acc.w, sl & 31);
        float pp = __shfl_sync(0xffffffffu, psum, g * NL);
        if (lane < NL) {
            acc.x += px;
            acc.y += py;
            acc.z += pz;
            acc.w += pw;
        }
        psum = (lane == 0) ? psum + pp : psum;
    }
    psum = __shfl_sync(0xffffffffu, psum, 0) + es;

    float4 v = make_float4(0.f, 0.f, 0.f, 0.f);
    if (lane < NL) {
        float inv = 1.0f / psum;
        v.x = acc.x * inv;
        v.y = acc.y * inv;
        v.z = acc.z * inv;
        v.w = acc.w * inv;
    }

    if (LSM) {
        float vm = -1e30f;
        if (lane < NL) vm = fmaxf(fmaxf(v.x, v.y), fmaxf(v.z, v.w));
#pragma unroll
        for (int o = 16; o; o >>= 1) vm = fmaxf(vm, __shfl_xor_sync(0xffffffffu, vm, o));
        float se = 0.f;
        if (lane < NL)
            se = __expf(v.x - vm) + __expf(v.y - vm) + __expf(v.z - vm) + __expf(v.w - vm);
#pragma unroll
        for (int o = 16; o; o >>= 1) se += __shfl_xor_sync(0xffffffffu, se, o);
        float l = vm + logf(se);
        if (lane < NL) {
            v.x -= l;
            v.y -= l;
            v.z -= l;
            v.w -= l;
            reinterpret_cast<float4*>(out)[(size_t)d * NL + cid] = v;
        }
    } else {
        if (lane < NL) {
            if (RELU) {
                v.x = fmaxf(v.x, 0.f);
                v.y = fmaxf(v.y, 0.f);
                v.z = fmaxf(v.z, 0.f);
                v.w = fmaxf(v.w, 0.f);
            }
            reinterpret_cast<float4*>(out)[(size_t)d * NL + cid] = v;
        }
    }
}

// ---------------- launch ----------------
extern "C" void kernel_launch(void* const* d_in, const int* in_sizes, int n_in,
                              void* d_out, int out_size) {
    (void)in_sizes;
    (void)n_in;
    (void)out_size;
    const float* x    = (const float*)d_in[0];
    const int*   ei   = (const int*)d_in[1];
    const float* W0   = (const float*)d_in[2];
    const float* att0 = (const float*)d_in[3];
    const float* W1   = (const float*)d_in[4];
    const float* att1 = (const float*)d_in[5];
    float* out = (float*)d_out;

    void *p;
    float *h0, *h1, *h2, *adst, *asrc, *wself;
    int *rowptr, *cursor, *colp, *bsum, *done;
    cudaGetSymbolAddress(&p, g_h0);     h0 = (float*)p;
    cudaGetSymbolAddress(&p, g_h1);     h1 = (float*)p;
    cudaGetSymbolAddress(&p, g_h2);     h2 = (float*)p;
    cudaGetSymbolAddress(&p, g_adst);   adst = (float*)p;
    cudaGetSymbolAddress(&p, g_asrc);   asrc = (float*)p;
    cudaGetSymbolAddress(&p, g_wself);  wself = (float*)p;
    cudaGetSymbolAddress(&p, g_rowptr); rowptr = (int*)p;
    cudaGetSymbolAddress(&p, g_cursor); cursor = (int*)p;
    cudaGetSymbolAddress(&p, g_col);    colp = (int*)p;
    cudaGetSymbolAddress(&p, g_bsum);   bsum = (int*)p;
    cudaGetSymbolAddress(&p, g_done);   done = (int*)p;

    cudaFuncSetAttribute(gemm1_mma_kernel,
                         cudaFuncAttributeMaxDynamicSharedMemorySize, SM_TOT);
    cudaFuncSetAttribute(gemm2_mma_kernel,
                         cudaFuncAttributeMaxDynamicSharedMemorySize, S2_TOT);

    const int TB = 256;
    int warp_blocks = (NN * 32 + TB - 1) / TB; // 12500

    // prep: convert W0/W1 once into pre-swizzled hi/lo buffers; reset bsum + done
    prep_w_kernel<<<11, TB>>>(W0, W1, bsum, done);

    // Layer-1 GEMM (M=64 tiles, 3 CTAs/SM) + degree histogram
    gemm1_mma_kernel<<<GB1, TB, SM_TOT>>>(x, att0, h0, adst, asrc, wself, ei, cursor);

    // CSR finalize: fused scan + gated scatter (one launch)
    scan_scatter_kernel<<<NBLK + SCB, 1024>>>(cursor, rowptr, cursor, bsum, ei, colp,
                                              done);

    // Layer 1 aggregation: 64ch, relu; also re-zeroes cursor for the next replay
    aggregate_kernel<64, true, false><<<warp_blocks, TB>>>(h0, adst, asrc, wself, rowptr,
                                                           colp, h1, cursor);

    // Layer 2: 64 -> 40 (warp mma.sync), then fused log_softmax aggregation
    gemm2_mma_kernel<<<GB2, TB, S2_TOT>>>(h1, att1, h2, adst, asrc, wself);
    aggregate_kernel<40, false, true><<<warp_blocks, TB>>>(h2, adst, asrc, wself, rowptr,
                                                           colp, out, nullptr);
}